// round 1
// baseline (speedup 1.0000x reference)
#include <cuda_runtime.h>
#include <math.h>

// ---------------- problem constants ----------------
#define Bv   2
#define Cch  256
#define Dd   32
#define Hh   32
#define Ww   32
#define Nn   32768           // D*H*W
#define Ss   256
#define TDd  512
#define NH   8
#define HD   32
#define SCALE 0.17677669529663687f   // 32^-0.5

// ---------------- scratch (static device allocs are allowed) ----------------
__device__ float g_krot[Bv * NH * Ss * HD];          // [b,h,s,hd]
__device__ float g_v   [Bv * NH * Ss * HD];          // [b,h,s,hd]
__device__ float g_qrot[(size_t)Bv * NH * Nn * HD];  // [b,h,n,hd]  64MB
__device__ float g_att [(size_t)Bv * Nn * Cch];      // [b,n,c]     64MB

// ---------------------------------------------------------------------------
// Kernel 1: text side. k = text@k_w+k_b ; v = text@v_w+v_b ;
// h = gelu(text@m1_w+m1_b) ; phase = h@m2_w+m2_b ; k_rot = rope(k, phase)
// One CTA handles 8 (b,s) rows; 256 threads = 256 output channels.
// ---------------------------------------------------------------------------
__global__ void text_kernel(const float* __restrict__ text,
                            const float* __restrict__ k_w, const float* __restrict__ k_b,
                            const float* __restrict__ v_w, const float* __restrict__ v_b,
                            const float* __restrict__ m1_w, const float* __restrict__ m1_b,
                            const float* __restrict__ m2_w, const float* __restrict__ m2_b)
{
    __shared__ float t_s[8][TDd];   // 16KB
    __shared__ float h_s[8][Cch];   // 8KB
    __shared__ float k_s[8][Cch];   // 8KB

    const int tid  = threadIdx.x;
    const int row0 = blockIdx.x * 8;          // global row = b*S + s

    #pragma unroll
    for (int r = 0; r < 8; r++) {
        t_s[r][tid]       = text[(size_t)(row0 + r) * TDd + tid];
        t_s[r][tid + 256] = text[(size_t)(row0 + r) * TDd + tid + 256];
    }
    __syncthreads();

    float ka[8], va[8], ha[8];
    #pragma unroll
    for (int r = 0; r < 8; r++) { ka[r] = k_b[tid]; va[r] = v_b[tid]; ha[r] = m1_b[tid]; }

    for (int i = 0; i < TDd; i++) {
        const float wk = k_w[i * Cch + tid];
        const float wv = v_w[i * Cch + tid];
        const float wm = m1_w[i * Cch + tid];
        #pragma unroll
        for (int r = 0; r < 8; r++) {
            const float t = t_s[r][i];
            ka[r] += t * wk;  va[r] += t * wv;  ha[r] += t * wm;
        }
    }

    #pragma unroll
    for (int r = 0; r < 8; r++) {
        const float x = ha[r];
        h_s[r][tid] = 0.5f * x * (1.0f + erff(x * 0.7071067811865475f));  // exact GELU
        k_s[r][tid] = ka[r];
    }
    __syncthreads();

    float pa[8];
    #pragma unroll
    for (int r = 0; r < 8; r++) pa[r] = m2_b[tid];
    for (int i = 0; i < Cch; i++) {
        const float wm2 = m2_w[i * Cch + tid];
        #pragma unroll
        for (int r = 0; r < 8; r++) pa[r] += h_s[r][i] * wm2;
    }

    const int j    = tid & 31;
    const int head = tid >> 5;
    const int part = (j < 16) ? tid + 16 : tid - 16;
    const float sgn = (j < 16) ? -1.0f : 1.0f;

    #pragma unroll
    for (int r = 0; r < 8; r++) {
        const int row = row0 + r;
        const int b = row >> 8;            // / S
        const int s = row & 255;           // % S
        float sf, cf;
        sincosf(pa[r], &sf, &cf);
        const float krot = k_s[r][tid] * cf + sgn * k_s[r][part] * sf;
        const int o = ((b * NH + head) * Ss + s) * HD + j;
        g_krot[o] = krot;
        g_v[o]    = va[r];
    }
}

// ---------------------------------------------------------------------------
// Kernel 2: Q projection + 3D RoPE.
// q[n,c] = sum_k fv[b,k,n] * q_w[k,c] + q_b[c]; then rope per (d,h,w,j).
// CTA: 32 tokens x 256 channels; 256 threads, 4x8 register tile each.
// ---------------------------------------------------------------------------
__global__ void qproj_kernel(const float* __restrict__ fv,
                             const float* __restrict__ qw,
                             const float* __restrict__ qb)
{
    __shared__ float A_s[8][32];        // 1KB
    __shared__ float W_s[8][Cch];       // 8KB
    __shared__ float q_s[32][Cch + 1];  // 32.9KB, padded -> conflict free

    const int tid = threadIdx.x;
    const int b   = blockIdx.x / (Nn / 32);
    const int n0  = (blockIdx.x % (Nn / 32)) * 32;
    const int cx  = tid & 31;
    const int ny  = tid >> 5;

    const float* __restrict__ fvb = fv + (size_t)b * Cch * Nn;

    float acc[4][8];
    #pragma unroll
    for (int t = 0; t < 4; t++)
        #pragma unroll
        for (int ci = 0; ci < 8; ci++) acc[t][ci] = 0.0f;

    for (int k0 = 0; k0 < Cch; k0 += 8) {
        A_s[tid >> 5][tid & 31] = fvb[(size_t)(k0 + (tid >> 5)) * Nn + n0 + (tid & 31)];
        #pragma unroll
        for (int r = 0; r < 8; r++) W_s[r][tid] = qw[(k0 + r) * Cch + tid];
        __syncthreads();

        #pragma unroll
        for (int kk = 0; kk < 8; kk++) {
            float a[4];
            #pragma unroll
            for (int t = 0; t < 4; t++) a[t] = A_s[kk][ny * 4 + t];
            #pragma unroll
            for (int ci = 0; ci < 8; ci++) {
                const float w = W_s[kk][cx + ci * 32];
                #pragma unroll
                for (int t = 0; t < 4; t++) acc[t][ci] += a[t] * w;
            }
        }
        __syncthreads();
    }

    #pragma unroll
    for (int t = 0; t < 4; t++)
        #pragma unroll
        for (int ci = 0; ci < 8; ci++)
            q_s[ny * 4 + t][cx + ci * 32] = acc[t][ci];
    __syncthreads();

    // epilogue: bias + 3D rope, thread tid owns channel c = tid for all 32 tokens
    const int c    = tid;
    const int j    = c & 31;
    const int head = c >> 5;
    // inv_freq for this j
    float invf;
    int sel;                 // 0 -> use d, 1 -> use h, 2 -> use w
    {
        float e;
        if (j < 10)      { const int jz = j;      const int idx = (jz < 5) ? jz : jz - 5; e = idx / 5.0f; sel = 0; }
        else if (j < 20) { const int jy = j - 10; const int idx = (jy < 5) ? jy : jy - 5; e = idx / 5.0f; sel = 1; }
        else             { const int jx = j - 20; const int idx = (jx < 6) ? jx : jx - 6; e = idx / 6.0f; sel = 2; }
        invf = expf(-e * 9.210340371976184f);     // 10000^{-e}
    }
    const int part  = (j < 16) ? c + 16 : c - 16;
    const float sgn = (j < 16) ? -1.0f : 1.0f;
    const float qbc = qb[c], qbp = qb[part];

    float* __restrict__ qo = g_qrot + (((size_t)(b * NH + head)) * Nn) * HD + j;
    for (int nn = 0; nn < 32; nn++) {
        const int n  = n0 + nn;
        const int dz = n >> 10;
        const int hy = (n >> 5) & 31;
        const int wx = n & 31;
        const float pos = (sel == 0) ? (float)dz : (sel == 1) ? (float)hy : (float)wx;
        float sf, cf;
        __sincosf(pos * invf, &sf, &cf);
        const float qv = q_s[nn][c]    + qbc;
        const float pv = q_s[nn][part] + qbp;
        qo[(size_t)n * HD] = qv * cf + sgn * pv * sf;
    }
}

// ---------------------------------------------------------------------------
// Kernel 3: attention. One thread = one query row, 128 rows/CTA.
// Online softmax (branch avoids the 32-mul rescale on non-max steps).
// ---------------------------------------------------------------------------
__global__ void attn_kernel()
{
    __shared__ float K_s[128][HD];   // 16KB
    __shared__ float V_s[128][HD];   // 16KB

    const int tid = threadIdx.x;
    const int n   = blockIdx.x * 128 + tid;
    const int h   = blockIdx.y;
    const int b   = blockIdx.z;

    const float* __restrict__ qp = g_qrot + (((size_t)(b * NH + h)) * Nn + n) * HD;
    float q[HD];
    #pragma unroll
    for (int i = 0; i < HD; i++) q[i] = qp[i] * SCALE;

    float m = -1e30f, l = 0.0f;
    float o[HD];
    #pragma unroll
    for (int i = 0; i < HD; i++) o[i] = 0.0f;

    for (int ch = 0; ch < 2; ch++) {
        const float* __restrict__ kp = g_krot + (((size_t)(b * NH + h)) * Ss + ch * 128 + tid) * HD;
        const float* __restrict__ vp = g_v    + (((size_t)(b * NH + h)) * Ss + ch * 128 + tid) * HD;
        #pragma unroll
        for (int i = 0; i < HD / 4; i++) {
            ((float4*)K_s[tid])[i] = ((const float4*)kp)[i];
            ((float4*)V_s[tid])[i] = ((const float4*)vp)[i];
        }
        __syncthreads();

        for (int s = 0; s < 128; s++) {
            float x = 0.0f;
            #pragma unroll
            for (int i = 0; i < HD; i++) x += q[i] * K_s[s][i];
            if (x <= m) {
                const float p = __expf(x - m);
                l += p;
                #pragma unroll
                for (int i = 0; i < HD; i++) o[i] += p * V_s[s][i];
            } else {
                const float corr = __expf(m - x);
                m = x;
                l = l * corr + 1.0f;
                #pragma unroll
                for (int i = 0; i < HD; i++) o[i] = o[i] * corr + V_s[s][i];
            }
        }
        __syncthreads();
    }

    const float inv = 1.0f / l;
    float* __restrict__ op = g_att + ((size_t)(b * Nn + n)) * Cch + h * HD;
    #pragma unroll
    for (int i = 0; i < HD; i++) op[i] = o[i] * inv;
}

// ---------------------------------------------------------------------------
// Kernel 4: O projection + transpose to [B,C,D,H,W].
// out[b,c,n] = sum_k att[b,n,k] * o_w[k,c] + o_b[c]
// ---------------------------------------------------------------------------
__global__ void oproj_kernel(const float* __restrict__ ow,
                             const float* __restrict__ ob,
                             float* __restrict__ out)
{
    __shared__ float A_s[8][33];
    __shared__ float W_s[8][Cch];
    __shared__ float o_s[32][Cch + 1];

    const int tid = threadIdx.x;
    const int b   = blockIdx.x / (Nn / 32);
    const int n0  = (blockIdx.x % (Nn / 32)) * 32;
    const int cx  = tid & 31;
    const int ny  = tid >> 5;

    float acc[4][8];
    #pragma unroll
    for (int t = 0; t < 4; t++)
        #pragma unroll
        for (int ci = 0; ci < 8; ci++) acc[t][ci] = 0.0f;

    for (int k0 = 0; k0 < Cch; k0 += 8) {
        // A[nn][kk] = att[b, n0+nn, k0+kk]; 8 contiguous floats per row
        A_s[tid & 7][tid >> 3] = g_att[((size_t)(b * Nn + n0 + (tid >> 3))) * Cch + k0 + (tid & 7)];
        #pragma unroll
        for (int r = 0; r < 8; r++) W_s[r][tid] = ow[(k0 + r) * Cch + tid];
        __syncthreads();

        #pragma unroll
        for (int kk = 0; kk < 8; kk++) {
            float a[4];
            #pragma unroll
            for (int t = 0; t < 4; t++) a[t] = A_s[kk][ny * 4 + t];
            #pragma unroll
            for (int ci = 0; ci < 8; ci++) {
                const float w = W_s[kk][cx + ci * 32];
                #pragma unroll
                for (int t = 0; t < 4; t++) acc[t][ci] += a[t] * w;
            }
        }
        __syncthreads();
    }

    #pragma unroll
    for (int t = 0; t < 4; t++)
        #pragma unroll
        for (int ci = 0; ci < 8; ci++)
            o_s[ny * 4 + t][cx + ci * 32] = acc[t][ci];
    __syncthreads();

    // coalesced transposed store: warp w writes channel c = it*8 + w over 32 tokens
    const int lane = tid & 31;
    const int grp  = tid >> 5;
    float* __restrict__ ob_out = out + (size_t)b * Cch * Nn + n0 + lane;
    #pragma unroll 4
    for (int it = 0; it < 32; it++) {
        const int c = it * 8 + grp;
        ob_out[(size_t)c * Nn] = o_s[lane][c] + ob[c];
    }
}

// ---------------------------------------------------------------------------
extern "C" void kernel_launch(void* const* d_in, const int* in_sizes, int n_in,
                              void* d_out, int out_size)
{
    const float* fused_visual = (const float*)d_in[0];
    const float* text_emb     = (const float*)d_in[1];
    const float* q_w = (const float*)d_in[2];
    const float* q_b = (const float*)d_in[3];
    const float* k_w = (const float*)d_in[4];
    const float* k_b = (const float*)d_in[5];
    const float* v_w = (const float*)d_in[6];
    const float* v_b = (const float*)d_in[7];
    const float* o_w = (const float*)d_in[8];
    const float* o_b = (const float*)d_in[9];
    const float* m1_w = (const float*)d_in[10];
    const float* m1_b = (const float*)d_in[11];
    const float* m2_w = (const float*)d_in[12];
    const float* m2_b = (const float*)d_in[13];
    float* out = (float*)d_out;

    text_kernel<<<(Bv * Ss) / 8, 256>>>(text_emb, k_w, k_b, v_w, v_b, m1_w, m1_b, m2_w, m2_b);
    qproj_kernel<<<Bv * (Nn / 32), 256>>>(fused_visual, q_w, q_b);
    attn_kernel<<<dim3(Nn / 128, NH, Bv), 128>>>();
    oproj_kernel<<<Bv * (Nn / 32), 256>>>(o_w, o_b, out);
}

// round 3
// speedup vs baseline: 1.7725x; 1.7725x over previous
#include <cuda_runtime.h>
#include <math.h>

// ---------------- problem constants ----------------
#define Bv   2
#define Cch  256
#define Nn   32768           // D*H*W
#define Ss   256
#define TDd  512
#define NH   8
#define HD   32
#define SCALE 0.17677669529663687f   // 32^-0.5

// ---------------- scratch ----------------
__device__ float g_krot[Bv * NH * Ss * HD];          // [b,h,s,hd]
__device__ float g_v   [Bv * NH * Ss * HD];          // [b,h,s,hd]
__device__ float g_qrot[(size_t)Bv * NH * Nn * HD];  // [b,h,n,hd]  64MB
__device__ float g_att [(size_t)Bv * Nn * Cch];      // [b,n,c]     64MB

// ---------------------------------------------------------------------------
// Kernel 1: text side (K/V proj, MLP phase, rope on K). 64 CTAs, tiny.
// ---------------------------------------------------------------------------
__global__ void text_kernel(const float* __restrict__ text,
                            const float* __restrict__ k_w, const float* __restrict__ k_b,
                            const float* __restrict__ v_w, const float* __restrict__ v_b,
                            const float* __restrict__ m1_w, const float* __restrict__ m1_b,
                            const float* __restrict__ m2_w, const float* __restrict__ m2_b)
{
    __shared__ float t_s[8][TDd];
    __shared__ float h_s[8][Cch];
    __shared__ float k_s[8][Cch];

    const int tid  = threadIdx.x;
    const int row0 = blockIdx.x * 8;

    #pragma unroll
    for (int r = 0; r < 8; r++) {
        t_s[r][tid]       = text[(size_t)(row0 + r) * TDd + tid];
        t_s[r][tid + 256] = text[(size_t)(row0 + r) * TDd + tid + 256];
    }
    __syncthreads();

    float ka[8], va[8], ha[8];
    #pragma unroll
    for (int r = 0; r < 8; r++) { ka[r] = k_b[tid]; va[r] = v_b[tid]; ha[r] = m1_b[tid]; }

    for (int i = 0; i < TDd; i++) {
        const float wk = k_w[i * Cch + tid];
        const float wv = v_w[i * Cch + tid];
        const float wm = m1_w[i * Cch + tid];
        #pragma unroll
        for (int r = 0; r < 8; r++) {
            const float t = t_s[r][i];
            ka[r] += t * wk;  va[r] += t * wv;  ha[r] += t * wm;
        }
    }

    #pragma unroll
    for (int r = 0; r < 8; r++) {
        const float x = ha[r];
        h_s[r][tid] = 0.5f * x * (1.0f + erff(x * 0.7071067811865475f));
        k_s[r][tid] = ka[r];
    }
    __syncthreads();

    float pa[8];
    #pragma unroll
    for (int r = 0; r < 8; r++) pa[r] = m2_b[tid];
    for (int i = 0; i < Cch; i++) {
        const float wm2 = m2_w[i * Cch + tid];
        #pragma unroll
        for (int r = 0; r < 8; r++) pa[r] += h_s[r][i] * wm2;
    }

    const int j    = tid & 31;
    const int head = tid >> 5;
    const int part = (j < 16) ? tid + 16 : tid - 16;
    const float sgn = (j < 16) ? -1.0f : 1.0f;

    #pragma unroll
    for (int r = 0; r < 8; r++) {
        const int row = row0 + r;
        const int b = row >> 8;
        const int s = row & 255;
        float sf, cf;
        sincosf(pa[r], &sf, &cf);
        const float krot = k_s[r][tid] * cf + sgn * k_s[r][part] * sf;
        const int o = ((b * NH + head) * Ss + s) * HD + j;
        g_krot[o] = krot;
        g_v[o]    = va[r];
    }
}

// ---------------------------------------------------------------------------
// Kernel 2: Q projection + 3D RoPE. 32 tokens x 256 ch per CTA, 256 threads.
// Vectorized inner loop: A via broadcast LDS.128, W via 4x LDS.64.
// ---------------------------------------------------------------------------
__global__ void qproj_kernel(const float* __restrict__ fv,
                             const float* __restrict__ qw,
                             const float* __restrict__ qb)
{
    __shared__ float A_s[8][32];
    __shared__ float W_s[8][Cch];
    __shared__ float q_s[32][258];   // even pad (float2-aligned)

    const int tid = threadIdx.x;
    const int b   = blockIdx.x / (Nn / 32);
    const int n0  = (blockIdx.x % (Nn / 32)) * 32;
    const int cx  = tid & 31;
    const int ny  = tid >> 5;

    const float* __restrict__ fvb = fv + (size_t)b * Cch * Nn;

    float acc[4][8];
    #pragma unroll
    for (int t = 0; t < 4; t++)
        #pragma unroll
        for (int ci = 0; ci < 8; ci++) acc[t][ci] = 0.0f;

    for (int k0 = 0; k0 < Cch; k0 += 8) {
        A_s[ny][cx] = fvb[(size_t)(k0 + ny) * Nn + n0 + cx];
        #pragma unroll
        for (int r = 0; r < 8; r++) W_s[r][tid] = qw[(k0 + r) * Cch + tid];
        __syncthreads();

        #pragma unroll
        for (int kk = 0; kk < 8; kk++) {
            const float4 a4 = *(const float4*)&A_s[kk][ny * 4];
            const float a[4] = {a4.x, a4.y, a4.z, a4.w};
            #pragma unroll
            for (int g = 0; g < 4; g++) {
                const float2 w = *(const float2*)&W_s[kk][cx * 2 + g * 64];
                #pragma unroll
                for (int t = 0; t < 4; t++) {
                    acc[t][g * 2]     += a[t] * w.x;
                    acc[t][g * 2 + 1] += a[t] * w.y;
                }
            }
        }
        __syncthreads();
    }

    #pragma unroll
    for (int t = 0; t < 4; t++)
        #pragma unroll
        for (int g = 0; g < 4; g++)
            *(float2*)&q_s[ny * 4 + t][cx * 2 + g * 64] =
                make_float2(acc[t][g * 2], acc[t][g * 2 + 1]);
    __syncthreads();

    // epilogue: bias + 3D rope; thread tid owns channel c = tid across 32 tokens
    const int c    = tid;
    const int j    = c & 31;
    const int head = c >> 5;
    float invf;
    int sel;
    {
        float e;
        if (j < 10)      { const int jz = j;      const int idx = (jz < 5) ? jz : jz - 5; e = idx / 5.0f; sel = 0; }
        else if (j < 20) { const int jy = j - 10; const int idx = (jy < 5) ? jy : jy - 5; e = idx / 5.0f; sel = 1; }
        else             { const int jx = j - 20; const int idx = (jx < 6) ? jx : jx - 6; e = idx / 6.0f; sel = 2; }
        invf = expf(-e * 9.210340371976184f);
    }
    const int part  = (j < 16) ? c + 16 : c - 16;
    const float sgn = (j < 16) ? -1.0f : 1.0f;
    const float qbc = qb[c], qbp = qb[part];

    float* __restrict__ qo = g_qrot + (((size_t)(b * NH + head)) * Nn) * HD + j;
    for (int nn = 0; nn < 32; nn++) {
        const int n  = n0 + nn;
        const int dz = n >> 10;
        const int hy = (n >> 5) & 31;
        const int wx = n & 31;
        const float pos = (sel == 0) ? (float)dz : (sel == 1) ? (float)hy : (float)wx;
        float sf, cf;
        __sincosf(pos * invf, &sf, &cf);
        const float qv = q_s[nn][c]    + qbc;
        const float pv = q_s[nn][part] + qbp;
        qo[(size_t)n * HD] = qv * cf + sgn * pv * sf;
    }
}

// ---------------------------------------------------------------------------
// Kernel 3: attention, GEMM-softmax-GEMM. CTA = 64 queries for one (b,h).
// 256 threads. Dynamic smem ~143KB.
// Layout (floats): QT[32][64] | KT[32][256] | V[256][32] | PT[256][68] | rinv[64]
// ---------------------------------------------------------------------------
#define AT_QT   0
#define AT_KT   2048
#define AT_V    10240
#define AT_PT   18432
#define AT_RINV 35840
#define AT_FLOATS 35904
#define AT_BYTES (AT_FLOATS * 4)

__global__ void __launch_bounds__(256, 1) attn_kernel()
{
    extern __shared__ float sm[];
    float* QT = sm + AT_QT;
    float* KT = sm + AT_KT;
    float* Vs = sm + AT_V;
    float* PT = sm + AT_PT;
    float* rinv = sm + AT_RINV;

    const int tid = threadIdx.x;
    const int n0  = blockIdx.x * 64;
    const int h   = blockIdx.y;
    const int b   = blockIdx.z;
    const size_t bh = (size_t)(b * NH + h);

    // ---- load Q (scaled, transposed) ----
    {
        const float* qsrc = g_qrot + (bh * Nn + n0) * HD;
        #pragma unroll
        for (int r = 0; r < 2; r++) {
            const int idx = tid + r * 256;          // float4 index
            const float4 f = ((const float4*)qsrc)[idx];
            const int q = idx >> 3;                  // row (query)
            const int i = (idx * 4) & 31;            // hd base
            QT[(i + 0) * 64 + q] = f.x * SCALE;
            QT[(i + 1) * 64 + q] = f.y * SCALE;
            QT[(i + 2) * 64 + q] = f.z * SCALE;
            QT[(i + 3) * 64 + q] = f.w * SCALE;
        }
    }
    // ---- load K transposed ----
    {
        const float* ksrc = g_krot + bh * Ss * HD;
        const float4* krow = (const float4*)(ksrc + tid * HD);
        #pragma unroll
        for (int j = 0; j < 8; j++) {
            const float4 f = krow[j];
            KT[(4 * j + 0) * 256 + tid] = f.x;
            KT[(4 * j + 1) * 256 + tid] = f.y;
            KT[(4 * j + 2) * 256 + tid] = f.z;
            KT[(4 * j + 3) * 256 + tid] = f.w;
        }
    }
    // ---- load V ----
    {
        const float4* vsrc = (const float4*)(g_v + bh * Ss * HD);
        #pragma unroll
        for (int r = 0; r < 8; r++)
            ((float4*)Vs)[tid + r * 256] = vsrc[tid + r * 256];
    }
    __syncthreads();

    // ---- score GEMM: thread (qg,kg) -> 4 queries x 16 keys ----
    const int qg = tid >> 4;     // 0..15
    const int kg = tid & 15;     // 0..15
    float acc[4][16];
    #pragma unroll
    for (int i = 0; i < 4; i++)
        #pragma unroll
        for (int j = 0; j < 16; j++) acc[i][j] = 0.0f;

    #pragma unroll 4
    for (int kk = 0; kk < 32; kk++) {
        const float4 a4 = *(const float4*)&QT[kk * 64 + qg * 4];
        const float a[4] = {a4.x, a4.y, a4.z, a4.w};
        const float4* krow = (const float4*)&KT[kk * 256];
        #pragma unroll
        for (int j = 0; j < 4; j++) {
            const float4 bv = krow[kg + 16 * j];
            #pragma unroll
            for (int i = 0; i < 4; i++) {
                acc[i][4 * j + 0] += a[i] * bv.x;
                acc[i][4 * j + 1] += a[i] * bv.y;
                acc[i][4 * j + 2] += a[i] * bv.z;
                acc[i][4 * j + 3] += a[i] * bv.w;
            }
        }
    }

    // ---- softmax over rows (16 lanes per query row) ----
    #pragma unroll
    for (int i = 0; i < 4; i++) {
        float m = acc[i][0];
        #pragma unroll
        for (int j = 1; j < 16; j++) m = fmaxf(m, acc[i][j]);
        #pragma unroll
        for (int msk = 1; msk < 16; msk <<= 1)
            m = fmaxf(m, __shfl_xor_sync(0xffffffffu, m, msk));
        float l = 0.0f;
        #pragma unroll
        for (int j = 0; j < 16; j++) {
            const float p = __expf(acc[i][j] - m);
            acc[i][j] = p;
            l += p;
        }
        #pragma unroll
        for (int msk = 1; msk < 16; msk <<= 1)
            l += __shfl_xor_sync(0xffffffffu, l, msk);
        if (kg == 0) rinv[qg * 4 + i] = 1.0f / l;
        // scatter p into PT[key][query]
        #pragma unroll
        for (int j = 0; j < 4; j++)
            #pragma unroll
            for (int c = 0; c < 4; c++)
                PT[(4 * (kg + 16 * j) + c) * 68 + qg * 4 + i] = acc[i][4 * j + c];
    }
    __syncthreads();

    // ---- AV GEMM: thread (qg2,hg) -> 4 queries x 2 hd ----
    const int qg2 = tid >> 4;
    const int hg  = tid & 15;
    float o0[4] = {0, 0, 0, 0};
    float o1[4] = {0, 0, 0, 0};

    #pragma unroll 8
    for (int k = 0; k < 256; k++) {
        const float4 a4 = *(const float4*)&PT[k * 68 + qg2 * 4];
        const float v0 = Vs[k * 32 + hg];
        const float v1 = Vs[k * 32 + hg + 16];
        o0[0] += a4.x * v0;  o1[0] += a4.x * v1;
        o0[1] += a4.y * v0;  o1[1] += a4.y * v1;
        o0[2] += a4.z * v0;  o1[2] += a4.z * v1;
        o0[3] += a4.w * v0;  o1[3] += a4.w * v1;
    }

    #pragma unroll
    for (int i = 0; i < 4; i++) {
        const float inv = rinv[qg2 * 4 + i];
        float* op = g_att + ((size_t)(b * Nn + n0 + qg2 * 4 + i)) * Cch + h * HD;
        op[hg]      = o0[i] * inv;
        op[hg + 16] = o1[i] * inv;
    }
}

// ---------------------------------------------------------------------------
// Kernel 4: O projection + transpose to [B,C,D,H,W].
// ---------------------------------------------------------------------------
__global__ void oproj_kernel(const float* __restrict__ ow,
                             const float* __restrict__ ob,
                             float* __restrict__ out)
{
    __shared__ float A_s[8][32];
    __shared__ float W_s[8][Cch];
    __shared__ float o_s[32][258];

    const int tid = threadIdx.x;
    const int b   = blockIdx.x / (Nn / 32);
    const int n0  = (blockIdx.x % (Nn / 32)) * 32;
    const int cx  = tid & 31;
    const int ny  = tid >> 5;

    float acc[4][8];
    #pragma unroll
    for (int t = 0; t < 4; t++)
        #pragma unroll
        for (int ci = 0; ci < 8; ci++) acc[t][ci] = 0.0f;

    for (int k0 = 0; k0 < Cch; k0 += 8) {
        A_s[tid & 7][tid >> 3] = g_att[((size_t)(b * Nn + n0 + (tid >> 3))) * Cch + k0 + (tid & 7)];
        #pragma unroll
        for (int r = 0; r < 8; r++) W_s[r][tid] = ow[(k0 + r) * Cch + tid];
        __syncthreads();

        #pragma unroll
        for (int kk = 0; kk < 8; kk++) {
            const float4 a4 = *(const float4*)&A_s[kk][ny * 4];
            const float a[4] = {a4.x, a4.y, a4.z, a4.w};
            #pragma unroll
            for (int g = 0; g < 4; g++) {
                const float2 w = *(const float2*)&W_s[kk][cx * 2 + g * 64];
                #pragma unroll
                for (int t = 0; t < 4; t++) {
                    acc[t][g * 2]     += a[t] * w.x;
                    acc[t][g * 2 + 1] += a[t] * w.y;
                }
            }
        }
        __syncthreads();
    }

    #pragma unroll
    for (int t = 0; t < 4; t++)
        #pragma unroll
        for (int g = 0; g < 4; g++)
            *(float2*)&o_s[ny * 4 + t][cx * 2 + g * 64] =
                make_float2(acc[t][g * 2], acc[t][g * 2 + 1]);
    __syncthreads();

    const int lane = tid & 31;
    const int grp  = tid >> 5;
    float* __restrict__ obp = out + (size_t)b * Cch * Nn + n0 + lane;
    #pragma unroll 4
    for (int it = 0; it < 32; it++) {
        const int c = it * 8 + grp;
        obp[(size_t)c * Nn] = o_s[lane][c] + ob[c];
    }
}

// ---------------------------------------------------------------------------
extern "C" void kernel_launch(void* const* d_in, const int* in_sizes, int n_in,
                              void* d_out, int out_size)
{
    const float* fused_visual = (const float*)d_in[0];
    const float* text_emb     = (const float*)d_in[1];
    const float* q_w = (const float*)d_in[2];
    const float* q_b = (const float*)d_in[3];
    const float* k_w = (const float*)d_in[4];
    const float* k_b = (const float*)d_in[5];
    const float* v_w = (const float*)d_in[6];
    const float* v_b = (const float*)d_in[7];
    const float* o_w = (const float*)d_in[8];
    const float* o_b = (const float*)d_in[9];
    const float* m1_w = (const float*)d_in[10];
    const float* m1_b = (const float*)d_in[11];
    const float* m2_w = (const float*)d_in[12];
    const float* m2_b = (const float*)d_in[13];
    float* out = (float*)d_out;

    static int smem_ok = -1;
    if (smem_ok < 0)
        smem_ok = (cudaFuncSetAttribute(attn_kernel,
                    cudaFuncAttributeMaxDynamicSharedMemorySize, AT_BYTES) == cudaSuccess);

    text_kernel<<<(Bv * Ss) / 8, 256>>>(text_emb, k_w, k_b, v_w, v_b, m1_w, m1_b, m2_w, m2_b);
    qproj_kernel<<<Bv * (Nn / 32), 256>>>(fused_visual, q_w, q_b);
    attn_kernel<<<dim3(Nn / 64, NH, Bv), 256, AT_BYTES>>>();
    oproj_kernel<<<Bv * (Nn / 32), 256>>>(o_w, o_b, out);
}

// round 6
// speedup vs baseline: 2.4733x; 1.3953x over previous
#include <cuda_runtime.h>
#include <math.h>

// ---------------- problem constants ----------------
#define Bv   2
#define Cch  256
#define Nn   32768           // D*H*W
#define Ss   256
#define TDd  512
#define NH   8
#define HD   32
#define SCALE 0.17677669529663687f   // 32^-0.5

// ---------------- scratch ----------------
__device__ float g_krot[Bv * NH * Ss * HD];          // [b,h,s,hd]
__device__ float g_v   [Bv * NH * Ss * HD];          // [b,h,s,hd]
__device__ float g_qrot[(size_t)Bv * NH * Nn * HD];  // [b,h,n,hd]  64MB
__device__ float g_att [(size_t)Bv * Nn * Cch];      // [b,n,c]     64MB

// ---------------- mma helpers ----------------
__device__ __forceinline__ unsigned f2tf(float x) {
    unsigned u;
    asm("cvt.rna.tf32.f32 %0, %1;" : "=r"(u) : "f"(x));
    return u;
}
__device__ __forceinline__ float tfval(float x) { return __uint_as_float(f2tf(x)); }

__device__ __forceinline__ void mma8(float c[4], const unsigned a[4],
                                     unsigned b0, unsigned b1) {
    asm volatile(
        "mma.sync.aligned.m16n8k8.row.col.f32.tf32.tf32.f32 "
        "{%0,%1,%2,%3},{%4,%5,%6,%7},{%8,%9},{%0,%1,%2,%3};"
        : "+f"(c[0]), "+f"(c[1]), "+f"(c[2]), "+f"(c[3])
        : "r"(a[0]), "r"(a[1]), "r"(a[2]), "r"(a[3]), "r"(b0), "r"(b1));
}

// ---------------------------------------------------------------------------
// Kernel 1: text side (K/V proj, MLP phase, rope on K). 64 CTAs, tiny. FFMA.
// ---------------------------------------------------------------------------
__global__ void text_kernel(const float* __restrict__ text,
                            const float* __restrict__ k_w, const float* __restrict__ k_b,
                            const float* __restrict__ v_w, const float* __restrict__ v_b,
                            const float* __restrict__ m1_w, const float* __restrict__ m1_b,
                            const float* __restrict__ m2_w, const float* __restrict__ m2_b)
{
    __shared__ float t_s[8][TDd];
    __shared__ float h_s[8][Cch];
    __shared__ float k_s[8][Cch];

    const int tid  = threadIdx.x;
    const int row0 = blockIdx.x * 8;

    #pragma unroll
    for (int r = 0; r < 8; r++) {
        t_s[r][tid]       = text[(size_t)(row0 + r) * TDd + tid];
        t_s[r][tid + 256] = text[(size_t)(row0 + r) * TDd + tid + 256];
    }
    __syncthreads();

    float ka[8], va[8], ha[8];
    #pragma unroll
    for (int r = 0; r < 8; r++) { ka[r] = k_b[tid]; va[r] = v_b[tid]; ha[r] = m1_b[tid]; }

    for (int i = 0; i < TDd; i++) {
        const float wk = k_w[i * Cch + tid];
        const float wv = v_w[i * Cch + tid];
        const float wm = m1_w[i * Cch + tid];
        #pragma unroll
        for (int r = 0; r < 8; r++) {
            const float t = t_s[r][i];
            ka[r] += t * wk;  va[r] += t * wv;  ha[r] += t * wm;
        }
    }

    #pragma unroll
    for (int r = 0; r < 8; r++) {
        const float x = ha[r];
        h_s[r][tid] = 0.5f * x * (1.0f + erff(x * 0.7071067811865475f));
        k_s[r][tid] = ka[r];
    }
    __syncthreads();

    float pa[8];
    #pragma unroll
    for (int r = 0; r < 8; r++) pa[r] = m2_b[tid];
    for (int i = 0; i < Cch; i++) {
        const float wm2 = m2_w[i * Cch + tid];
        #pragma unroll
        for (int r = 0; r < 8; r++) pa[r] += h_s[r][i] * wm2;
    }

    const int j    = tid & 31;
    const int head = tid >> 5;
    const int part = (j < 16) ? tid + 16 : tid - 16;
    const float sgn = (j < 16) ? -1.0f : 1.0f;

    #pragma unroll
    for (int r = 0; r < 8; r++) {
        const int row = row0 + r;
        const int b = row >> 8;
        const int s = row & 255;
        float sf, cf;
        sincosf(pa[r], &sf, &cf);
        const float krot = k_s[r][tid] * cf + sgn * k_s[r][part] * sf;
        const int o = ((b * NH + head) * Ss + s) * HD + j;
        g_krot[o] = krot;
        g_v[o]    = va[r];
    }
}

// ---------------------------------------------------------------------------
// Kernel 2: Q projection + 3D RoPE, TF32 mma. CTA = 64 tokens x 256 cols.
// smem: A[64][33] | WT[256][33]  (overlaid by OUT[64][258] for epilogue)
// ---------------------------------------------------------------------------
#define PJ_A    0
#define PJ_W    2112
#define PJ_FLOATS 16512           // 64*258 out buffer dominates
#define PJ_BYTES (PJ_FLOATS * 4)

__global__ void __launch_bounds__(256) qproj_kernel(const float* __restrict__ fv,
                                                    const float* __restrict__ qw,
                                                    const float* __restrict__ qb)
{
    extern __shared__ float sm[];
    float* As = sm + PJ_A;      // [64][33]
    float* Ws = sm + PJ_W;      // [256][33]

    const int tid  = threadIdx.x;
    const int w    = tid >> 5;
    const int lane = tid & 31;
    const int g    = lane >> 2;
    const int tg   = lane & 3;
    const int b    = blockIdx.x >> 9;
    const int n0   = (blockIdx.x & 511) << 6;
    const int qg   = w >> 1;         // 16-token group
    const int ch   = w & 1;          // 128-col half
    const int qr   = qg * 16 + g;

    const float* __restrict__ fvb = fv + (size_t)b * Cch * Nn;

    float acc[16][4];
    #pragma unroll
    for (int nt = 0; nt < 16; nt++)
        #pragma unroll
        for (int i = 0; i < 4; i++) acc[nt][i] = 0.0f;

    for (int k0 = 0; k0 < Cch; k0 += 32) {
        // stage A = fv^T tile [64 tok][32 k], transposed on load
        #pragma unroll
        for (int r = 0; r < 8; r++) {
            const int e  = tid + r * 256;
            const int kk = e >> 6;
            const int nn = e & 63;
            As[nn * 33 + kk] = tfval(fvb[(size_t)(k0 + kk) * Nn + n0 + nn]);
        }
        // stage W^T tile [256 c][32 k]
        #pragma unroll
        for (int r = 0; r < 8; r++) {
            const int e  = tid + r * 256;
            const int kk = e >> 6;
            const int c4 = (e & 63) * 4;
            const float4 f = *(const float4*)(qw + (size_t)(k0 + kk) * Cch + c4);
            Ws[(c4 + 0) * 33 + kk] = tfval(f.x);
            Ws[(c4 + 1) * 33 + kk] = tfval(f.y);
            Ws[(c4 + 2) * 33 + kk] = tfval(f.z);
            Ws[(c4 + 3) * 33 + kk] = tfval(f.w);
        }
        __syncthreads();

        unsigned a[4][4];
        #pragma unroll
        for (int ks = 0; ks < 4; ks++) {
            const int base = ks * 8 + tg;
            a[ks][0] = __float_as_uint(As[qr * 33 + base]);
            a[ks][1] = __float_as_uint(As[(qr + 8) * 33 + base]);
            a[ks][2] = __float_as_uint(As[qr * 33 + base + 4]);
            a[ks][3] = __float_as_uint(As[(qr + 8) * 33 + base + 4]);
        }
        #pragma unroll
        for (int nt = 0; nt < 16; nt++) {
            const int c0 = ch * 128 + nt * 8 + g;
            #pragma unroll
            for (int ks = 0; ks < 4; ks++) {
                const unsigned b0 = __float_as_uint(Ws[c0 * 33 + ks * 8 + tg]);
                const unsigned b1 = __float_as_uint(Ws[c0 * 33 + ks * 8 + tg + 4]);
                mma8(acc[nt], a[ks], b0, b1);
            }
        }
        __syncthreads();
    }

    // write accums into OUT[64][258] (overlays A/W — safe post-sync)
    #pragma unroll
    for (int nt = 0; nt < 16; nt++) {
        const int col = ch * 128 + nt * 8 + 2 * tg;
        *(float2*)&sm[qr * 258 + col]       = make_float2(acc[nt][0], acc[nt][1]);
        *(float2*)&sm[(qr + 8) * 258 + col] = make_float2(acc[nt][2], acc[nt][3]);
    }
    __syncthreads();

    // epilogue: bias + 3D rope; thread = channel c for 64 tokens
    const int c    = tid;
    const int j    = c & 31;
    const int head = c >> 5;
    float invf;
    int sel;
    {
        float e;
        if (j < 10)      { const int jz = j;      const int idx = (jz < 5) ? jz : jz - 5; e = idx / 5.0f; sel = 0; }
        else if (j < 20) { const int jy = j - 10; const int idx = (jy < 5) ? jy : jy - 5; e = idx / 5.0f; sel = 1; }
        else             { const int jx = j - 20; const int idx = (jx < 6) ? jx : jx - 6; e = idx / 6.0f; sel = 2; }
        invf = expf(-e * 9.210340371976184f);
    }
    const int part  = (j < 16) ? c + 16 : c - 16;
    const float sgn = (j < 16) ? -1.0f : 1.0f;
    const float qbc = qb[c], qbp = qb[part];

    float* __restrict__ qo = g_qrot + (((size_t)(b * NH + head)) * Nn) * HD + j;
    for (int nn = 0; nn < 64; nn++) {
        const int n  = n0 + nn;
        const int dz = n >> 10;
        const int hy = (n >> 5) & 31;
        const int wx = n & 31;
        const float pos = (sel == 0) ? (float)dz : (sel == 1) ? (float)hy : (float)wx;
        float sf, cf;
        __sincosf(pos * invf, &sf, &cf);
        const float qv = sm[nn * 258 + c]    + qbc;
        const float pv = sm[nn * 258 + part] + qbp;
        qo[(size_t)n * HD] = qv * cf + sgn * pv * sf;
    }
}

// ---------------------------------------------------------------------------
// Kernel 3: attention with TF32 mma. CTA = 64 queries for one (b,h).
// smem floats: Qs[64][36] | Ks[256][36] | VT[32][260] | Ps[64][260] | rinv[64]
// ---------------------------------------------------------------------------
#define AQ   0
#define AK   2304
#define AVT  11520
#define AP   19840
#define AR   36480
#define AT_FLOATS 36544
#define AT_BYTES (AT_FLOATS * 4)

__global__ void __launch_bounds__(256, 1) attn_kernel()
{
    extern __shared__ float sm[];
    float* Qs = sm + AQ;     // [64][36]   tf32
    float* Ks = sm + AK;     // [256][36]  tf32
    float* VT = sm + AVT;    // [32][260]  tf32 (hd-major)
    float* Ps = sm + AP;     // [64][260]  scores -> tf32 probs
    float* rinv = sm + AR;   // [64]

    const int tid  = threadIdx.x;
    const int w    = tid >> 5;
    const int lane = tid & 31;
    const int g    = lane >> 2;
    const int tg   = lane & 3;
    const int n0   = blockIdx.x * 64;
    const int h    = blockIdx.y;
    const int b    = blockIdx.z;
    const size_t bh = (size_t)(b * NH + h);

    // ---- stage Q (scaled + tf32) ----
    {
        const float4* qsrc = (const float4*)(g_qrot + (bh * Nn + n0) * HD);
        #pragma unroll
        for (int r = 0; r < 2; r++) {
            const int idx = tid + r * 256;
            const float4 f = qsrc[idx];
            const int qq = idx >> 3;
            const int c4 = (idx & 7) * 4;
            Qs[qq * 36 + c4 + 0] = tfval(f.x * SCALE);
            Qs[qq * 36 + c4 + 1] = tfval(f.y * SCALE);
            Qs[qq * 36 + c4 + 2] = tfval(f.z * SCALE);
            Qs[qq * 36 + c4 + 3] = tfval(f.w * SCALE);
        }
    }
    // ---- stage K (tf32) ----
    {
        const float4* ksrc = (const float4*)(g_krot + bh * Ss * HD);
        #pragma unroll
        for (int r = 0; r < 8; r++) {
            const int idx = tid + r * 256;
            const float4 f = ksrc[idx];
            const int kk = idx >> 3;
            const int c4 = (idx & 7) * 4;
            Ks[kk * 36 + c4 + 0] = tfval(f.x);
            Ks[kk * 36 + c4 + 1] = tfval(f.y);
            Ks[kk * 36 + c4 + 2] = tfval(f.z);
            Ks[kk * 36 + c4 + 3] = tfval(f.w);
        }
    }
    // ---- stage V transposed (tf32) ----
    {
        const float4* vsrc = (const float4*)(g_v + bh * Ss * HD);
        #pragma unroll
        for (int r = 0; r < 8; r++) {
            const int idx = tid + r * 256;
            const float4 f = vsrc[idx];
            const int s  = idx >> 3;
            const int c4 = (idx & 7) * 4;
            VT[(c4 + 0) * 260 + s] = tfval(f.x);
            VT[(c4 + 1) * 260 + s] = tfval(f.y);
            VT[(c4 + 2) * 260 + s] = tfval(f.z);
            VT[(c4 + 3) * 260 + s] = tfval(f.w);
        }
    }
    __syncthreads();

    // ---- QK^T mma: warp = (16 queries) x (128 keys) ----
    const int qg = w >> 1;
    const int kh = w & 1;
    const int qr = qg * 16 + g;
    {
        unsigned a[4][4];
        #pragma unroll
        for (int ks = 0; ks < 4; ks++) {
            const int base = ks * 8 + tg;
            a[ks][0] = __float_as_uint(Qs[qr * 36 + base]);
            a[ks][1] = __float_as_uint(Qs[(qr + 8) * 36 + base]);
            a[ks][2] = __float_as_uint(Qs[qr * 36 + base + 4]);
            a[ks][3] = __float_as_uint(Qs[(qr + 8) * 36 + base + 4]);
        }
        float c[16][4];
        #pragma unroll
        for (int nt = 0; nt < 16; nt++)
            #pragma unroll
            for (int i = 0; i < 4; i++) c[nt][i] = 0.0f;

        #pragma unroll
        for (int nt = 0; nt < 16; nt++) {
            const int k0 = kh * 128 + nt * 8 + g;
            #pragma unroll
            for (int ks = 0; ks < 4; ks++) {
                const unsigned b0 = __float_as_uint(Ks[k0 * 36 + ks * 8 + tg]);
                const unsigned b1 = __float_as_uint(Ks[k0 * 36 + ks * 8 + tg + 4]);
                mma8(c[nt], a[ks], b0, b1);
            }
        }
        #pragma unroll
        for (int nt = 0; nt < 16; nt++) {
            const int col = kh * 128 + nt * 8 + 2 * tg;
            *(float2*)&Ps[qr * 260 + col]       = make_float2(c[nt][0], c[nt][1]);
            *(float2*)&Ps[(qr + 8) * 260 + col] = make_float2(c[nt][2], c[nt][3]);
        }
    }
    __syncthreads();

    // ---- softmax: 4 threads per query row, 64 keys each ----
    {
        const int row  = tid >> 2;
        const int part = tid & 3;
        float* pr = Ps + row * 260 + part * 64;

        float m = -1e30f;
        #pragma unroll
        for (int j4 = 0; j4 < 16; j4++) {
            const float4 v = *(const float4*)&pr[j4 * 4];
            m = fmaxf(m, fmaxf(fmaxf(v.x, v.y), fmaxf(v.z, v.w)));
        }
        m = fmaxf(m, __shfl_xor_sync(0xffffffffu, m, 1));
        m = fmaxf(m, __shfl_xor_sync(0xffffffffu, m, 2));

        float l = 0.0f;
        #pragma unroll
        for (int j4 = 0; j4 < 16; j4++) {
            float4 v = *(const float4*)&pr[j4 * 4];
            const float e0 = __expf(v.x - m), e1 = __expf(v.y - m);
            const float e2 = __expf(v.z - m), e3 = __expf(v.w - m);
            l += (e0 + e1) + (e2 + e3);
            v.x = tfval(e0); v.y = tfval(e1); v.z = tfval(e2); v.w = tfval(e3);
            *(float4*)&pr[j4 * 4] = v;
        }
        l += __shfl_xor_sync(0xffffffffu, l, 1);
        l += __shfl_xor_sync(0xffffffffu, l, 2);
        if (part == 0) rinv[row] = 1.0f / l;
    }
    __syncthreads();

    // ---- P @ V mma: warp = (16 queries) x (16 hd) ----
    {
        const int hh  = w & 1;
        const int hd0 = hh * 16;
        float o[2][4];
        #pragma unroll
        for (int nt = 0; nt < 2; nt++)
            #pragma unroll
            for (int i = 0; i < 4; i++) o[nt][i] = 0.0f;

        #pragma unroll 4
        for (int ks = 0; ks < 32; ks++) {
            const int base = ks * 8 + tg;
            unsigned a[4];
            a[0] = __float_as_uint(Ps[qr * 260 + base]);
            a[1] = __float_as_uint(Ps[(qr + 8) * 260 + base]);
            a[2] = __float_as_uint(Ps[qr * 260 + base + 4]);
            a[3] = __float_as_uint(Ps[(qr + 8) * 260 + base + 4]);
            #pragma unroll
            for (int nt = 0; nt < 2; nt++) {
                const int hr = hd0 + nt * 8 + g;
                const unsigned b0 = __float_as_uint(VT[hr * 260 + base]);
                const unsigned b1 = __float_as_uint(VT[hr * 260 + base + 4]);
                mma8(o[nt], a, b0, b1);
            }
        }

        const float rv0 = rinv[qr];
        const float rv1 = rinv[qr + 8];
        #pragma unroll
        for (int nt = 0; nt < 2; nt++) {
            const int hd = hd0 + nt * 8 + 2 * tg;
            float* p0 = g_att + ((size_t)(b * Nn + n0 + qr)) * Cch + h * HD + hd;
            float* p1 = g_att + ((size_t)(b * Nn + n0 + qr + 8)) * Cch + h * HD + hd;
            *(float2*)p0 = make_float2(o[nt][0] * rv0, o[nt][1] * rv0);
            *(float2*)p1 = make_float2(o[nt][2] * rv1, o[nt][3] * rv1);
        }
    }
}

// ---------------------------------------------------------------------------
// Kernel 4: O projection + transpose, TF32 mma. CTA = 64 tokens x 256 cols.
// ---------------------------------------------------------------------------
__global__ void __launch_bounds__(256) oproj_kernel(const float* __restrict__ ow,
                                                    const float* __restrict__ ob,
                                                    float* __restrict__ out)
{
    extern __shared__ float sm[];
    float* As = sm + PJ_A;      // [64][33]
    float* Ws = sm + PJ_W;      // [256][33]

    const int tid  = threadIdx.x;
    const int w    = tid >> 5;
    const int lane = tid & 31;
    const int g    = lane >> 2;
    const int tg   = lane & 3;
    const int b    = blockIdx.x >> 9;
    const int n0   = (blockIdx.x & 511) << 6;
    const int qg   = w >> 1;
    const int ch   = w & 1;
    const int qr   = qg * 16 + g;

    float acc[16][4];
    #pragma unroll
    for (int nt = 0; nt < 16; nt++)
        #pragma unroll
        for (int i = 0; i < 4; i++) acc[nt][i] = 0.0f;

    for (int k0 = 0; k0 < Cch; k0 += 32) {
        // stage A from g_att (row-major, no transpose)
        #pragma unroll
        for (int r = 0; r < 8; r++) {
            const int e  = tid + r * 256;
            const int nn = e >> 5;
            const int kk = e & 31;
            As[nn * 33 + kk] = tfval(g_att[((size_t)(b * Nn + n0 + nn)) * Cch + k0 + kk]);
        }
        // stage W^T
        #pragma unroll
        for (int r = 0; r < 8; r++) {
            const int e  = tid + r * 256;
            const int kk = e >> 6;
            const int c4 = (e & 63) * 4;
            const float4 f = *(const float4*)(ow + (size_t)(k0 + kk) * Cch + c4);
            Ws[(c4 + 0) * 33 + kk] = tfval(f.x);
            Ws[(c4 + 1) * 33 + kk] = tfval(f.y);
            Ws[(c4 + 2) * 33 + kk] = tfval(f.z);
            Ws[(c4 + 3) * 33 + kk] = tfval(f.w);
        }
        __syncthreads();

        unsigned a[4][4];
        #pragma unroll
        for (int ks = 0; ks < 4; ks++) {
            const int base = ks * 8 + tg;
            a[ks][0] = __float_as_uint(As[qr * 33 + base]);
            a[ks][1] = __float_as_uint(As[(qr + 8) * 33 + base]);
            a[ks][2] = __float_as_uint(As[qr * 33 + base + 4]);
            a[ks][3] = __float_as_uint(As[(qr + 8) * 33 + base + 4]);
        }
        #pragma unroll
        for (int nt = 0; nt < 16; nt++) {
            const int c0 = ch * 128 + nt * 8 + g;
            #pragma unroll
            for (int ks = 0; ks < 4; ks++) {
                const unsigned b0 = __float_as_uint(Ws[c0 * 33 + ks * 8 + tg]);
                const unsigned b1 = __float_as_uint(Ws[c0 * 33 + ks * 8 + tg + 4]);
                mma8(acc[nt], a[ks], b0, b1);
            }
        }
        __syncthreads();
    }

    #pragma unroll
    for (int nt = 0; nt < 16; nt++) {
        const int col = ch * 128 + nt * 8 + 2 * tg;
        *(float2*)&sm[qr * 258 + col]       = make_float2(acc[nt][0], acc[nt][1]);
        *(float2*)&sm[(qr + 8) * 258 + col] = make_float2(acc[nt][2], acc[nt][3]);
    }
    __syncthreads();

    // transposed coalesced store: out[b][c][n0 + token]
    const int grp = tid >> 5;
    float* __restrict__ obp = out + (size_t)b * Cch * Nn + n0 + lane;
    #pragma unroll 4
    for (int it = 0; it < 32; it++) {
        const int c = it * 8 + grp;
        const float bias = ob[c];
        obp[(size_t)c * Nn]      = sm[lane * 258 + c] + bias;
        obp[(size_t)c * Nn + 32] = sm[(lane + 32) * 258 + c] + bias;
    }
}

// ---------------------------------------------------------------------------
extern "C" void kernel_launch(void* const* d_in, const int* in_sizes, int n_in,
                              void* d_out, int out_size)
{
    const float* fused_visual = (const float*)d_in[0];
    const float* text_emb     = (const float*)d_in[1];
    const float* q_w = (const float*)d_in[2];
    const float* q_b = (const float*)d_in[3];
    const float* k_w = (const float*)d_in[4];
    const float* k_b = (const float*)d_in[5];
    const float* v_w = (const float*)d_in[6];
    const float* v_b = (const float*)d_in[7];
    const float* o_w = (const float*)d_in[8];
    const float* o_b = (const float*)d_in[9];
    const float* m1_w = (const float*)d_in[10];
    const float* m1_b = (const float*)d_in[11];
    const float* m2_w = (const float*)d_in[12];
    const float* m2_b = (const float*)d_in[13];
    float* out = (float*)d_out;

    static int smem_ok = -1;
    if (smem_ok < 0) {
        cudaFuncSetAttribute(attn_kernel,  cudaFuncAttributeMaxDynamicSharedMemorySize, AT_BYTES);
        cudaFuncSetAttribute(qproj_kernel, cudaFuncAttributeMaxDynamicSharedMemorySize, PJ_BYTES);
        cudaFuncSetAttribute(oproj_kernel, cudaFuncAttributeMaxDynamicSharedMemorySize, PJ_BYTES);
        smem_ok = 1;
    }

    text_kernel<<<(Bv * Ss) / 8, 256>>>(text_emb, k_w, k_b, v_w, v_b, m1_w, m1_b, m2_w, m2_b);
    qproj_kernel<<<Bv * (Nn / 64), 256, PJ_BYTES>>>(fused_visual, q_w, q_b);
    attn_kernel<<<dim3(Nn / 64, NH, Bv), 256, AT_BYTES>>>();
    oproj_kernel<<<Bv * (Nn / 64), 256, PJ_BYTES>>>(o_w, o_b, out);
}

// round 7
// speedup vs baseline: 3.9812x; 1.6097x over previous
#include <cuda_runtime.h>
#include <math.h>

// ---------------- problem constants ----------------
#define Bv   2
#define Cch  256
#define Nn   32768           // D*H*W
#define Ss   256
#define TDd  512
#define NH   8
#define HD   32
#define SCALE 0.17677669529663687f   // 32^-0.5

// ---------------- scratch ----------------
__device__ float g_krot[Bv * NH * Ss * HD];          // [b,h,s,hd]
__device__ float g_v   [Bv * NH * Ss * HD];          // [b,h,s,hd]
__device__ float g_qrot[(size_t)Bv * NH * Nn * HD];  // [b,h,n,hd]  64MB
__device__ float g_att [(size_t)Bv * Nn * Cch];      // [b,n,c]     64MB

// ---------------- mma helpers ----------------
__device__ __forceinline__ unsigned f2tf(float x) {
    unsigned u;
    asm("cvt.rna.tf32.f32 %0, %1;" : "=r"(u) : "f"(x));
    return u;
}
__device__ __forceinline__ float tfval(float x) { return __uint_as_float(f2tf(x)); }

__device__ __forceinline__ void mma8(float c[4], const unsigned a[4],
                                     unsigned b0, unsigned b1) {
    asm volatile(
        "mma.sync.aligned.m16n8k8.row.col.f32.tf32.tf32.f32 "
        "{%0,%1,%2,%3},{%4,%5,%6,%7},{%8,%9},{%0,%1,%2,%3};"
        : "+f"(c[0]), "+f"(c[1]), "+f"(c[2]), "+f"(c[3])
        : "r"(a[0]), "r"(a[1]), "r"(a[2]), "r"(a[3]), "r"(b0), "r"(b1));
}

// ---------------------------------------------------------------------------
// Kernel 1: text side (K/V proj, MLP phase, rope on K). 64 CTAs, tiny. FFMA.
// ---------------------------------------------------------------------------
__global__ void text_kernel(const float* __restrict__ text,
                            const float* __restrict__ k_w, const float* __restrict__ k_b,
                            const float* __restrict__ v_w, const float* __restrict__ v_b,
                            const float* __restrict__ m1_w, const float* __restrict__ m1_b,
                            const float* __restrict__ m2_w, const float* __restrict__ m2_b)
{
    __shared__ float t_s[8][TDd];
    __shared__ float h_s[8][Cch];
    __shared__ float k_s[8][Cch];

    const int tid  = threadIdx.x;
    const int row0 = blockIdx.x * 8;

    #pragma unroll
    for (int r = 0; r < 8; r++) {
        t_s[r][tid]       = text[(size_t)(row0 + r) * TDd + tid];
        t_s[r][tid + 256] = text[(size_t)(row0 + r) * TDd + tid + 256];
    }
    __syncthreads();

    float ka[8], va[8], ha[8];
    #pragma unroll
    for (int r = 0; r < 8; r++) { ka[r] = k_b[tid]; va[r] = v_b[tid]; ha[r] = m1_b[tid]; }

    for (int i = 0; i < TDd; i++) {
        const float wk = k_w[i * Cch + tid];
        const float wv = v_w[i * Cch + tid];
        const float wm = m1_w[i * Cch + tid];
        #pragma unroll
        for (int r = 0; r < 8; r++) {
            const float t = t_s[r][i];
            ka[r] += t * wk;  va[r] += t * wv;  ha[r] += t * wm;
        }
    }

    #pragma unroll
    for (int r = 0; r < 8; r++) {
        const float x = ha[r];
        h_s[r][tid] = 0.5f * x * (1.0f + erff(x * 0.7071067811865475f));
        k_s[r][tid] = ka[r];
    }
    __syncthreads();

    float pa[8];
    #pragma unroll
    for (int r = 0; r < 8; r++) pa[r] = m2_b[tid];
    for (int i = 0; i < Cch; i++) {
        const float wm2 = m2_w[i * Cch + tid];
        #pragma unroll
        for (int r = 0; r < 8; r++) pa[r] += h_s[r][i] * wm2;
    }

    const int j    = tid & 31;
    const int head = tid >> 5;
    const int part = (j < 16) ? tid + 16 : tid - 16;
    const float sgn = (j < 16) ? -1.0f : 1.0f;

    #pragma unroll
    for (int r = 0; r < 8; r++) {
        const int row = row0 + r;
        const int b = row >> 8;
        const int s = row & 255;
        float sf, cf;
        sincosf(pa[r], &sf, &cf);
        const float krot = k_s[r][tid] * cf + sgn * k_s[r][part] * sf;
        const int o = ((b * NH + head) * Ss + s) * HD + j;
        g_krot[o] = krot;
        g_v[o]    = va[r];
    }
}

// ---------------------------------------------------------------------------
// Projection kernels, TF32 mma. CTA = 64 tokens x 256 cols, 256 threads.
// smem: As[64][36] | Wrow[32][264]  (overlaid by OUT[64][258] for epilogue)
// As stride 36 -> conflict-free a-frag loads; Wrow stride 264 (==8 mod 32)
// -> conflict-free b-frag loads AND conflict-free STS.128 staging.
// ---------------------------------------------------------------------------
#define PJ_A    0
#define PJ_W    2304                  // 64*36
#define PJ_FLOATS 16512               // out 64*258 dominates (> 2304+8448)
#define PJ_BYTES (PJ_FLOATS * 4)

__global__ void __launch_bounds__(256) qproj_kernel(const float* __restrict__ fv,
                                                    const float* __restrict__ qw,
                                                    const float* __restrict__ qb)
{
    extern __shared__ float sm[];
    float* As = sm + PJ_A;      // [64][36]
    float* Ws = sm + PJ_W;      // [32][264]

    const int tid  = threadIdx.x;
    const int w    = tid >> 5;
    const int lane = tid & 31;
    const int g    = lane >> 2;
    const int tg   = lane & 3;
    const int b    = blockIdx.x >> 9;
    const int n0   = (blockIdx.x & 511) << 6;
    const int qg   = w >> 1;
    const int ch   = w & 1;
    const int qr   = qg * 16 + g;

    const float* __restrict__ fvb = fv + (size_t)b * Cch * Nn;

    float acc[16][4];
    #pragma unroll
    for (int nt = 0; nt < 16; nt++)
        #pragma unroll
        for (int i = 0; i < 4; i++) acc[nt][i] = 0.0f;

    for (int k0 = 0; k0 < Cch; k0 += 32) {
        // stage A = fv^T tile [64 tok][32 k], transposed on load
        #pragma unroll
        for (int r = 0; r < 8; r++) {
            const int e  = tid + r * 256;
            const int kk = e >> 6;
            const int nn = e & 63;
            As[nn * 36 + kk] = tfval(fvb[(size_t)(k0 + kk) * Nn + n0 + nn]);
        }
        // stage W row-major [32 k][256 c], coalesced LDG.128 + STS.128
        #pragma unroll
        for (int r = 0; r < 8; r++) {
            const int e  = tid + r * 256;
            const int kk = e >> 6;
            const int c4 = (e & 63) * 4;
            const float4 f = *(const float4*)(qw + (size_t)(k0 + kk) * Cch + c4);
            float4 t;
            t.x = tfval(f.x); t.y = tfval(f.y); t.z = tfval(f.z); t.w = tfval(f.w);
            *(float4*)&Ws[kk * 264 + c4] = t;
        }
        __syncthreads();

        unsigned a[4][4];
        #pragma unroll
        for (int ks = 0; ks < 4; ks++) {
            const int base = ks * 8 + tg;
            a[ks][0] = __float_as_uint(As[qr * 36 + base]);
            a[ks][1] = __float_as_uint(As[(qr + 8) * 36 + base]);
            a[ks][2] = __float_as_uint(As[qr * 36 + base + 4]);
            a[ks][3] = __float_as_uint(As[(qr + 8) * 36 + base + 4]);
        }
        #pragma unroll
        for (int nt = 0; nt < 16; nt++) {
            const int c0 = ch * 128 + nt * 8 + g;
            #pragma unroll
            for (int ks = 0; ks < 4; ks++) {
                const unsigned b0 = __float_as_uint(Ws[(ks * 8 + tg) * 264 + c0]);
                const unsigned b1 = __float_as_uint(Ws[(ks * 8 + tg + 4) * 264 + c0]);
                mma8(acc[nt], a[ks], b0, b1);
            }
        }
        __syncthreads();
    }

    // write accums into OUT[64][258] (overlays A/W — safe post-sync)
    #pragma unroll
    for (int nt = 0; nt < 16; nt++) {
        const int col = ch * 128 + nt * 8 + 2 * tg;
        *(float2*)&sm[qr * 258 + col]       = make_float2(acc[nt][0], acc[nt][1]);
        *(float2*)&sm[(qr + 8) * 258 + col] = make_float2(acc[nt][2], acc[nt][3]);
    }
    __syncthreads();

    // epilogue: bias + 3D rope; thread = channel c for 64 tokens
    const int c    = tid;
    const int j    = c & 31;
    const int head = c >> 5;
    float invf;
    int sel;
    {
        float e;
        if (j < 10)      { const int jz = j;      const int idx = (jz < 5) ? jz : jz - 5; e = idx / 5.0f; sel = 0; }
        else if (j < 20) { const int jy = j - 10; const int idx = (jy < 5) ? jy : jy - 5; e = idx / 5.0f; sel = 1; }
        else             { const int jx = j - 20; const int idx = (jx < 6) ? jx : jx - 6; e = idx / 6.0f; sel = 2; }
        invf = expf(-e * 9.210340371976184f);
    }
    const int part  = (j < 16) ? c + 16 : c - 16;
    const float sgn = (j < 16) ? -1.0f : 1.0f;
    const float qbc = qb[c], qbp = qb[part];

    float* __restrict__ qo = g_qrot + (((size_t)(b * NH + head)) * Nn) * HD + j;
    for (int nn = 0; nn < 64; nn++) {
        const int n  = n0 + nn;
        const int dz = n >> 10;
        const int hy = (n >> 5) & 31;
        const int wx = n & 31;
        const float pos = (sel == 0) ? (float)dz : (sel == 1) ? (float)hy : (float)wx;
        float sf, cf;
        __sincosf(pos * invf, &sf, &cf);
        const float qv = sm[nn * 258 + c]    + qbc;
        const float pv = sm[nn * 258 + part] + qbp;
        qo[(size_t)n * HD] = qv * cf + sgn * pv * sf;
    }
}

// ---------------------------------------------------------------------------
// Kernel 3: flash-style attention, TF32 mma. CTA = 64 queries (4 warps),
// each warp owns 16 queries x full 256 keys with online softmax in registers.
// smem: Qs[64][36] | Kf[256][36] | Vs[256][40] | Ps[64][68] (per-chunk probs)
// All fragment loads bank-conflict-free by stride choice.
// ---------------------------------------------------------------------------
#define AQ   0
#define AK   2304                    // 64*36
#define AV   (AK + 256*36)           // 11520
#define AP   (AV + 256*40)           // 21760
#define AT_FLOATS (AP + 64*68)       // 26112
#define AT_BYTES (AT_FLOATS * 4)     // 104448

__global__ void __launch_bounds__(128) attn_kernel()
{
    extern __shared__ float sm[];
    float* Qs = sm + AQ;     // [64][36]
    float* Kf = sm + AK;     // [256][36]
    float* Vs = sm + AV;     // [256][40]
    float* Ps = sm + AP;     // [64][68]

    const int tid  = threadIdx.x;
    const int w    = tid >> 5;       // 0..3 = query group
    const int lane = tid & 31;
    const int g    = lane >> 2;
    const int tg   = lane & 3;
    const int n0   = blockIdx.x * 64;
    const int h    = blockIdx.y;
    const int b    = blockIdx.z;
    const size_t bh = (size_t)(b * NH + h);
    const int qr   = w * 16 + g;

    // ---- stage Q (scaled + tf32), K, V ----
    {
        const float4* qsrc = (const float4*)(g_qrot + (bh * Nn + n0) * HD);
        #pragma unroll
        for (int r = 0; r < 4; r++) {
            const int idx = tid + r * 128;
            const float4 f = qsrc[idx];
            const int row = idx >> 3;
            const int c4  = (idx & 7) * 4;
            float4 t;
            t.x = tfval(f.x * SCALE); t.y = tfval(f.y * SCALE);
            t.z = tfval(f.z * SCALE); t.w = tfval(f.w * SCALE);
            *(float4*)&Qs[row * 36 + c4] = t;
        }
        const float4* ksrc = (const float4*)(g_krot + bh * Ss * HD);
        const float4* vsrc = (const float4*)(g_v    + bh * Ss * HD);
        #pragma unroll
        for (int r = 0; r < 16; r++) {
            const int idx = tid + r * 128;
            const int key = idx >> 3;
            const int c4  = (idx & 7) * 4;
            const float4 fk = ksrc[idx];
            float4 tk;
            tk.x = tfval(fk.x); tk.y = tfval(fk.y); tk.z = tfval(fk.z); tk.w = tfval(fk.w);
            *(float4*)&Kf[key * 36 + c4] = tk;
            const float4 fv4 = vsrc[idx];
            float4 tv;
            tv.x = tfval(fv4.x); tv.y = tfval(fv4.y); tv.z = tfval(fv4.z); tv.w = tfval(fv4.w);
            *(float4*)&Vs[key * 40 + c4] = tv;
        }
    }
    __syncthreads();

    // ---- load Q a-frags (held for whole kernel) ----
    unsigned aq[4][4];
    #pragma unroll
    for (int ks = 0; ks < 4; ks++) {
        const int base = ks * 8 + tg;
        aq[ks][0] = __float_as_uint(Qs[qr * 36 + base]);
        aq[ks][1] = __float_as_uint(Qs[(qr + 8) * 36 + base]);
        aq[ks][2] = __float_as_uint(Qs[qr * 36 + base + 4]);
        aq[ks][3] = __float_as_uint(Qs[(qr + 8) * 36 + base + 4]);
    }

    float m0 = -1e30f, m1 = -1e30f, l0 = 0.0f, l1 = 0.0f;
    float o[4][4];
    #pragma unroll
    for (int nt = 0; nt < 4; nt++)
        #pragma unroll
        for (int i = 0; i < 4; i++) o[nt][i] = 0.0f;

    #pragma unroll
    for (int ch = 0; ch < 4; ch++) {
        // ---- QK^T for 64-key chunk ----
        float c[8][4];
        #pragma unroll
        for (int nt = 0; nt < 8; nt++)
            #pragma unroll
            for (int i = 0; i < 4; i++) c[nt][i] = 0.0f;

        #pragma unroll
        for (int nt = 0; nt < 8; nt++) {
            const int k0 = ch * 64 + nt * 8 + g;
            #pragma unroll
            for (int ks = 0; ks < 4; ks++) {
                const unsigned b0 = __float_as_uint(Kf[k0 * 36 + ks * 8 + tg]);
                const unsigned b1 = __float_as_uint(Kf[k0 * 36 + ks * 8 + tg + 4]);
                mma8(c[nt], aq[ks], b0, b1);
            }
        }

        // ---- chunk row max (rows qr, qr+8 live in tg-quad) ----
        float cm0 = -1e30f, cm1 = -1e30f;
        #pragma unroll
        for (int nt = 0; nt < 8; nt++) {
            cm0 = fmaxf(cm0, fmaxf(c[nt][0], c[nt][1]));
            cm1 = fmaxf(cm1, fmaxf(c[nt][2], c[nt][3]));
        }
        cm0 = fmaxf(cm0, __shfl_xor_sync(0xffffffffu, cm0, 1));
        cm0 = fmaxf(cm0, __shfl_xor_sync(0xffffffffu, cm0, 2));
        cm1 = fmaxf(cm1, __shfl_xor_sync(0xffffffffu, cm1, 1));
        cm1 = fmaxf(cm1, __shfl_xor_sync(0xffffffffu, cm1, 2));

        const float mn0 = fmaxf(m0, cm0);
        const float mn1 = fmaxf(m1, cm1);
        const float sc0 = __expf(m0 - mn0);
        const float sc1 = __expf(m1 - mn1);
        m0 = mn0; m1 = mn1;

        // ---- exp + row sums; convert to tf32 probs ----
        float s0 = 0.0f, s1 = 0.0f;
        #pragma unroll
        for (int nt = 0; nt < 8; nt++) {
            const float p0 = __expf(c[nt][0] - mn0);
            const float p1 = __expf(c[nt][1] - mn0);
            const float p2 = __expf(c[nt][2] - mn1);
            const float p3 = __expf(c[nt][3] - mn1);
            s0 += p0 + p1;  s1 += p2 + p3;
            c[nt][0] = tfval(p0); c[nt][1] = tfval(p1);
            c[nt][2] = tfval(p2); c[nt][3] = tfval(p3);
        }
        s0 += __shfl_xor_sync(0xffffffffu, s0, 1);
        s0 += __shfl_xor_sync(0xffffffffu, s0, 2);
        s1 += __shfl_xor_sync(0xffffffffu, s1, 1);
        s1 += __shfl_xor_sync(0xffffffffu, s1, 2);
        l0 = l0 * sc0 + s0;
        l1 = l1 * sc1 + s1;

        // ---- rescale O accumulators ----
        #pragma unroll
        for (int nt = 0; nt < 4; nt++) {
            o[nt][0] *= sc0;  o[nt][1] *= sc0;
            o[nt][2] *= sc1;  o[nt][3] *= sc1;
        }

        // ---- write chunk probs to per-warp Ps rows (warp-private) ----
        #pragma unroll
        for (int nt = 0; nt < 8; nt++) {
            *(float2*)&Ps[qr * 68 + nt * 8 + 2 * tg]       = make_float2(c[nt][0], c[nt][1]);
            *(float2*)&Ps[(qr + 8) * 68 + nt * 8 + 2 * tg] = make_float2(c[nt][2], c[nt][3]);
        }
        __syncwarp();

        // ---- P @ V for this chunk ----
        #pragma unroll
        for (int s = 0; s < 8; s++) {
            unsigned a[4];
            a[0] = __float_as_uint(Ps[qr * 68 + s * 8 + tg]);
            a[1] = __float_as_uint(Ps[(qr + 8) * 68 + s * 8 + tg]);
            a[2] = __float_as_uint(Ps[qr * 68 + s * 8 + tg + 4]);
            a[3] = __float_as_uint(Ps[(qr + 8) * 68 + s * 8 + tg + 4]);
            const int kk = ch * 64 + s * 8;
            #pragma unroll
            for (int nt = 0; nt < 4; nt++) {
                const unsigned b0 = __float_as_uint(Vs[(kk + tg) * 40 + nt * 8 + g]);
                const unsigned b1 = __float_as_uint(Vs[(kk + tg + 4) * 40 + nt * 8 + g]);
                mma8(o[nt], a, b0, b1);
            }
        }
        __syncwarp();
    }

    // ---- epilogue: normalize + store ----
    const float r0 = 1.0f / l0;
    const float r1 = 1.0f / l1;
    #pragma unroll
    for (int nt = 0; nt < 4; nt++) {
        const int hd = nt * 8 + 2 * tg;
        float* p0 = g_att + ((size_t)(b * Nn + n0 + qr)) * Cch + h * HD + hd;
        float* p1 = g_att + ((size_t)(b * Nn + n0 + qr + 8)) * Cch + h * HD + hd;
        *(float2*)p0 = make_float2(o[nt][0] * r0, o[nt][1] * r0);
        *(float2*)p1 = make_float2(o[nt][2] * r1, o[nt][3] * r1);
    }
}

// ---------------------------------------------------------------------------
// Kernel 4: O projection + transpose, TF32 mma. CTA = 64 tokens x 256 cols.
// ---------------------------------------------------------------------------
__global__ void __launch_bounds__(256) oproj_kernel(const float* __restrict__ ow,
                                                    const float* __restrict__ ob,
                                                    float* __restrict__ out)
{
    extern __shared__ float sm[];
    float* As = sm + PJ_A;      // [64][36]
    float* Ws = sm + PJ_W;      // [32][264]

    const int tid  = threadIdx.x;
    const int w    = tid >> 5;
    const int lane = tid & 31;
    const int g    = lane >> 2;
    const int tg   = lane & 3;
    const int b    = blockIdx.x >> 9;
    const int n0   = (blockIdx.x & 511) << 6;
    const int qg   = w >> 1;
    const int ch   = w & 1;
    const int qr   = qg * 16 + g;

    float acc[16][4];
    #pragma unroll
    for (int nt = 0; nt < 16; nt++)
        #pragma unroll
        for (int i = 0; i < 4; i++) acc[nt][i] = 0.0f;

    for (int k0 = 0; k0 < Cch; k0 += 32) {
        // stage A from g_att (row-major, coalesced, conflict-free STS)
        #pragma unroll
        for (int r = 0; r < 8; r++) {
            const int e  = tid + r * 256;
            const int nn = e >> 5;
            const int kk = e & 31;
            As[nn * 36 + kk] = tfval(g_att[((size_t)(b * Nn + n0 + nn)) * Cch + k0 + kk]);
        }
        // stage W row-major [32 k][256 c]
        #pragma unroll
        for (int r = 0; r < 8; r++) {
            const int e  = tid + r * 256;
            const int kk = e >> 6;
            const int c4 = (e & 63) * 4;
            const float4 f = *(const float4*)(ow + (size_t)(k0 + kk) * Cch + c4);
            float4 t;
            t.x = tfval(f.x); t.y = tfval(f.y); t.z = tfval(f.z); t.w = tfval(f.w);
            *(float4*)&Ws[kk * 264 + c4] = t;
        }
        __syncthreads();

        unsigned a[4][4];
        #pragma unroll
        for (int ks = 0; ks < 4; ks++) {
            const int base = ks * 8 + tg;
            a[ks][0] = __float_as_uint(As[qr * 36 + base]);
            a[ks][1] = __float_as_uint(As[(qr + 8) * 36 + base]);
            a[ks][2] = __float_as_uint(As[qr * 36 + base + 4]);
            a[ks][3] = __float_as_uint(As[(qr + 8) * 36 + base + 4]);
        }
        #pragma unroll
        for (int nt = 0; nt < 16; nt++) {
            const int c0 = ch * 128 + nt * 8 + g;
            #pragma unroll
            for (int ks = 0; ks < 4; ks++) {
                const unsigned b0 = __float_as_uint(Ws[(ks * 8 + tg) * 264 + c0]);
                const unsigned b1 = __float_as_uint(Ws[(ks * 8 + tg + 4) * 264 + c0]);
                mma8(acc[nt], a[ks], b0, b1);
            }
        }
        __syncthreads();
    }

    #pragma unroll
    for (int nt = 0; nt < 16; nt++) {
        const int col = ch * 128 + nt * 8 + 2 * tg;
        *(float2*)&sm[qr * 258 + col]       = make_float2(acc[nt][0], acc[nt][1]);
        *(float2*)&sm[(qr + 8) * 258 + col] = make_float2(acc[nt][2], acc[nt][3]);
    }
    __syncthreads();

    // transposed coalesced store: out[b][c][n0 + token]
    const int grp = tid >> 5;
    float* __restrict__ obp = out + (size_t)b * Cch * Nn + n0 + lane;
    #pragma unroll 4
    for (int it = 0; it < 32; it++) {
        const int c = it * 8 + grp;
        const float bias = ob[c];
        obp[(size_t)c * Nn]      = sm[lane * 258 + c] + bias;
        obp[(size_t)c * Nn + 32] = sm[(lane + 32) * 258 + c] + bias;
    }
}

// ---------------------------------------------------------------------------
extern "C" void kernel_launch(void* const* d_in, const int* in_sizes, int n_in,
                              void* d_out, int out_size)
{
    const float* fused_visual = (const float*)d_in[0];
    const float* text_emb     = (const float*)d_in[1];
    const float* q_w = (const float*)d_in[2];
    const float* q_b = (const float*)d_in[3];
    const float* k_w = (const float*)d_in[4];
    const float* k_b = (const float*)d_in[5];
    const float* v_w = (const float*)d_in[6];
    const float* v_b = (const float*)d_in[7];
    const float* o_w = (const float*)d_in[8];
    const float* o_b = (const float*)d_in[9];
    const float* m1_w = (const float*)d_in[10];
    const float* m1_b = (const float*)d_in[11];
    const float* m2_w = (const float*)d_in[12];
    const float* m2_b = (const float*)d_in[13];
    float* out = (float*)d_out;

    static int smem_ok = -1;
    if (smem_ok < 0) {
        cudaFuncSetAttribute(attn_kernel,  cudaFuncAttributeMaxDynamicSharedMemorySize, AT_BYTES);
        cudaFuncSetAttribute(qproj_kernel, cudaFuncAttributeMaxDynamicSharedMemorySize, PJ_BYTES);
        cudaFuncSetAttribute(oproj_kernel, cudaFuncAttributeMaxDynamicSharedMemorySize, PJ_BYTES);
        smem_ok = 1;
    }

    text_kernel<<<(Bv * Ss) / 8, 256>>>(text_emb, k_w, k_b, v_w, v_b, m1_w, m1_b, m2_w, m2_b);
    qproj_kernel<<<Bv * (Nn / 64), 256, PJ_BYTES>>>(fused_visual, q_w, q_b);
    attn_kernel<<<dim3(Nn / 64, NH, Bv), 128, AT_BYTES>>>();
    oproj_kernel<<<Bv * (Nn / 64), 256, PJ_BYTES>>>(o_w, o_b, out);
}

// round 9
// speedup vs baseline: 4.0153x; 1.0086x over previous
#include <cuda_runtime.h>
#include <math.h>

// ---------------- problem constants ----------------
#define Bv   2
#define Cch  256
#define Nn   32768           // D*H*W
#define Ss   256
#define TDd  512
#define NH   8
#define HD   32
#define SCALE 0.17677669529663687f   // 32^-0.5

// ---------------- scratch ----------------
__device__ float g_krot[Bv * NH * Ss * HD];          // [b,h,s,hd]
__device__ float g_v   [Bv * NH * Ss * HD];          // [b,h,s,hd]
__device__ float g_qrot[(size_t)Bv * NH * Nn * HD];  // [b,h,n,hd]  64MB
__device__ float g_att [(size_t)Bv * Nn * Cch];      // [b,n,c]     64MB

// ---------------- mma helpers ----------------
__device__ __forceinline__ unsigned f2tf(float x) {
    unsigned u;
    asm("cvt.rna.tf32.f32 %0, %1;" : "=r"(u) : "f"(x));
    return u;
}
__device__ __forceinline__ float tfval(float x) { return __uint_as_float(f2tf(x)); }

__device__ __forceinline__ void mma8(float c[4], const unsigned a[4],
                                     unsigned b0, unsigned b1) {
    asm volatile(
        "mma.sync.aligned.m16n8k8.row.col.f32.tf32.tf32.f32 "
        "{%0,%1,%2,%3},{%4,%5,%6,%7},{%8,%9},{%0,%1,%2,%3};"
        : "+f"(c[0]), "+f"(c[1]), "+f"(c[2]), "+f"(c[3])
        : "r"(a[0]), "r"(a[1]), "r"(a[2]), "r"(a[3]), "r"(b0), "r"(b1));
}

// ---------------------------------------------------------------------------
// Kernel 1: text side (K/V proj, MLP phase, rope on K). 64 CTAs, tiny. FFMA.
// ---------------------------------------------------------------------------
__global__ void text_kernel(const float* __restrict__ text,
                            const float* __restrict__ k_w, const float* __restrict__ k_b,
                            const float* __restrict__ v_w, const float* __restrict__ v_b,
                            const float* __restrict__ m1_w, const float* __restrict__ m1_b,
                            const float* __restrict__ m2_w, const float* __restrict__ m2_b)
{
    __shared__ float t_s[8][TDd];
    __shared__ float h_s[8][Cch];
    __shared__ float k_s[8][Cch];

    const int tid  = threadIdx.x;
    const int row0 = blockIdx.x * 8;

    #pragma unroll
    for (int r = 0; r < 8; r++) {
        t_s[r][tid]       = text[(size_t)(row0 + r) * TDd + tid];
        t_s[r][tid + 256] = text[(size_t)(row0 + r) * TDd + tid + 256];
    }
    __syncthreads();

    float ka[8], va[8], ha[8];
    #pragma unroll
    for (int r = 0; r < 8; r++) { ka[r] = k_b[tid]; va[r] = v_b[tid]; ha[r] = m1_b[tid]; }

    for (int i = 0; i < TDd; i++) {
        const float wk = k_w[i * Cch + tid];
        const float wv = v_w[i * Cch + tid];
        const float wm = m1_w[i * Cch + tid];
        #pragma unroll
        for (int r = 0; r < 8; r++) {
            const float t = t_s[r][i];
            ka[r] += t * wk;  va[r] += t * wv;  ha[r] += t * wm;
        }
    }

    #pragma unroll
    for (int r = 0; r < 8; r++) {
        const float x = ha[r];
        h_s[r][tid] = 0.5f * x * (1.0f + erff(x * 0.7071067811865475f));
        k_s[r][tid] = ka[r];
    }
    __syncthreads();

    float pa[8];
    #pragma unroll
    for (int r = 0; r < 8; r++) pa[r] = m2_b[tid];
    for (int i = 0; i < Cch; i++) {
        const float wm2 = m2_w[i * Cch + tid];
        #pragma unroll
        for (int r = 0; r < 8; r++) pa[r] += h_s[r][i] * wm2;
    }

    const int j    = tid & 31;
    const int head = tid >> 5;
    const int part = (j < 16) ? tid + 16 : tid - 16;
    const float sgn = (j < 16) ? -1.0f : 1.0f;

    #pragma unroll
    for (int r = 0; r < 8; r++) {
        const int row = row0 + r;
        const int b = row >> 8;
        const int s = row & 255;
        float sf, cf;
        sincosf(pa[r], &sf, &cf);
        const float krot = k_s[r][tid] * cf + sgn * k_s[r][part] * sf;
        const int o = ((b * NH + head) * Ss + s) * HD + j;
        g_krot[o] = krot;
        g_v[o]    = va[r];
    }
}

// ---------------------------------------------------------------------------
// Projection kernels, TF32 mma. CTA = 64 tokens x 256 cols, 256 threads.
// Warp tile: 32 tokens x 64 cols (2 mt x 8 nt) -> 96 frag LDS per 64 mma.
// smem: As[64][36] | Wrow[32][264]  (overlaid by OUT[64][258] for epilogue)
// qproj additionally keeps a rope cos/sin table at PJ_TAB (never overlaid).
// ---------------------------------------------------------------------------
#define PJ_A    0
#define PJ_W    2304                  // 64*36
#define PJ_OUTF 16512                 // 64*258
#define PJ_TAB  16512                 // rope tables: cos[1024] | sin[1024]
#define QJ_FLOATS (PJ_TAB + 2048)     // 18560
#define QJ_BYTES (QJ_FLOATS * 4)
#define OJ_BYTES (PJ_OUTF * 4)

__global__ void __launch_bounds__(256, 2) qproj_kernel(const float* __restrict__ fv,
                                                       const float* __restrict__ qw,
                                                       const float* __restrict__ qb)
{
    extern __shared__ float sm[];
    float* As = sm + PJ_A;      // [64][36]
    float* Ws = sm + PJ_W;      // [32][264]
    float* TB = sm + PJ_TAB;    // cos[32][32] | sin[32][32]

    const int tid  = threadIdx.x;
    const int w    = tid >> 5;
    const int lane = tid & 31;
    const int g    = lane >> 2;
    const int tg   = lane & 3;
    const int b    = blockIdx.x >> 9;
    const int n0   = (blockIdx.x & 511) << 6;
    const int mg   = w >> 2;          // 32-token group
    const int cg   = w & 3;           // 64-col group
    const int m0   = mg * 32;

    // ---- build rope tables (4 sincos per thread) ----
    #pragma unroll
    for (int e = 0; e < 4; e++) {
        const int idx = tid + e * 256;     // 0..1023
        const int pos = idx >> 5;
        const int jj  = idx & 31;
        float ex;
        if (jj < 10)      { const int z = jj;      ex = ((z < 5) ? z : z - 5) / 5.0f; }
        else if (jj < 20) { const int y = jj - 10; ex = ((y < 5) ? y : y - 5) / 5.0f; }
        else              { const int x = jj - 20; ex = ((x < 6) ? x : x - 6) / 6.0f; }
        const float invf = expf(-ex * 9.210340371976184f);
        float sf, cf;
        __sincosf((float)pos * invf, &sf, &cf);
        TB[idx]        = cf;
        TB[1024 + idx] = sf;
    }

    const float* __restrict__ fvb = fv + (size_t)b * Cch * Nn;

    float acc[2][8][4];
    #pragma unroll
    for (int mt = 0; mt < 2; mt++)
        #pragma unroll
        for (int nt = 0; nt < 8; nt++)
            #pragma unroll
            for (int i = 0; i < 4; i++) acc[mt][nt][i] = 0.0f;

    for (int k0 = 0; k0 < Cch; k0 += 32) {
        // stage A = fv^T tile [64 tok][32 k], transposed on load
        #pragma unroll
        for (int r = 0; r < 8; r++) {
            const int e  = tid + r * 256;
            const int kk = e >> 6;
            const int nn = e & 63;
            As[nn * 36 + kk] = tfval(fvb[(size_t)(k0 + kk) * Nn + n0 + nn]);
        }
        // stage W row-major [32 k][256 c]
        #pragma unroll
        for (int r = 0; r < 8; r++) {
            const int e  = tid + r * 256;
            const int kk = e >> 6;
            const int c4 = (e & 63) * 4;
            const float4 f = *(const float4*)(qw + (size_t)(k0 + kk) * Cch + c4);
            float4 t;
            t.x = tfval(f.x); t.y = tfval(f.y); t.z = tfval(f.z); t.w = tfval(f.w);
            *(float4*)&Ws[kk * 264 + c4] = t;
        }
        __syncthreads();

        unsigned a[2][4][4];
        #pragma unroll
        for (int mt = 0; mt < 2; mt++) {
            const int row = m0 + mt * 16 + g;
            #pragma unroll
            for (int ks = 0; ks < 4; ks++) {
                const int base = ks * 8 + tg;
                a[mt][ks][0] = __float_as_uint(As[row * 36 + base]);
                a[mt][ks][1] = __float_as_uint(As[(row + 8) * 36 + base]);
                a[mt][ks][2] = __float_as_uint(As[row * 36 + base + 4]);
                a[mt][ks][3] = __float_as_uint(As[(row + 8) * 36 + base + 4]);
            }
        }
        #pragma unroll
        for (int nt = 0; nt < 8; nt++) {
            const int c0 = cg * 64 + nt * 8 + g;
            #pragma unroll
            for (int ks = 0; ks < 4; ks++) {
                const unsigned b0 = __float_as_uint(Ws[(ks * 8 + tg) * 264 + c0]);
                const unsigned b1 = __float_as_uint(Ws[(ks * 8 + tg + 4) * 264 + c0]);
                mma8(acc[0][nt], a[0][ks], b0, b1);
                mma8(acc[1][nt], a[1][ks], b0, b1);
            }
        }
        __syncthreads();
    }

    // write accums into OUT[64][258]
    #pragma unroll
    for (int mt = 0; mt < 2; mt++) {
        const int row = m0 + mt * 16 + g;
        #pragma unroll
        for (int nt = 0; nt < 8; nt++) {
            const int col = cg * 64 + nt * 8 + 2 * tg;
            *(float2*)&sm[row * 258 + col]       = make_float2(acc[mt][nt][0], acc[mt][nt][1]);
            *(float2*)&sm[(row + 8) * 258 + col] = make_float2(acc[mt][nt][2], acc[mt][nt][3]);
        }
    }
    __syncthreads();

    // epilogue: bias + 3D rope via table; thread = channel c for 64 tokens
    const int c    = tid;
    const int j    = c & 31;
    const int head = c >> 5;
    const int sel  = (j < 10) ? 0 : (j < 20) ? 1 : 2;
    const int part  = (j < 16) ? c + 16 : c - 16;
    const float sgn = (j < 16) ? -1.0f : 1.0f;
    const float qbc = qb[c], qbp = qb[part];

    float* __restrict__ qo = g_qrot + (((size_t)(b * NH + head)) * Nn) * HD + j;
    for (int nn = 0; nn < 64; nn++) {
        const int n  = n0 + nn;
        const int dz = n >> 10;
        const int hy = (n >> 5) & 31;
        const int wx = n & 31;
        const int posv = (sel == 0) ? dz : (sel == 1) ? hy : wx;
        const float cf = TB[posv * 32 + j];
        const float sf = TB[1024 + posv * 32 + j];
        const float qv = sm[nn * 258 + c]    + qbc;
        const float pv = sm[nn * 258 + part] + qbp;
        qo[(size_t)n * HD] = qv * cf + sgn * pv * sf;
    }
}

// ---------------------------------------------------------------------------
// Kernel 3: flash-style attention, TF32 mma. CTA = 64 queries (4 warps),
// each warp owns 16 queries x full 256 keys with online softmax in registers.
// ---------------------------------------------------------------------------
#define AQ   0
#define AK   2304                    // 64*36
#define AV   (AK + 256*36)           // 11520
#define AP   (AV + 256*40)           // 21760
#define AT_FLOATS (AP + 64*68)       // 26112
#define AT_BYTES (AT_FLOATS * 4)     // 104448

__global__ void __launch_bounds__(128) attn_kernel()
{
    extern __shared__ float sm[];
    float* Qs = sm + AQ;     // [64][36]
    float* Kf = sm + AK;     // [256][36]
    float* Vs = sm + AV;     // [256][40]
    float* Ps = sm + AP;     // [64][68]

    const int tid  = threadIdx.x;
    const int w    = tid >> 5;
    const int lane = tid & 31;
    const int g    = lane >> 2;
    const int tg   = lane & 3;
    const int n0   = blockIdx.x * 64;
    const int h    = blockIdx.y;
    const int b    = blockIdx.z;
    const size_t bh = (size_t)(b * NH + h);
    const int qr   = w * 16 + g;

    // ---- stage Q (scaled + tf32), K, V ----
    {
        const float4* qsrc = (const float4*)(g_qrot + (bh * Nn + n0) * HD);
        #pragma unroll
        for (int r = 0; r < 4; r++) {
            const int idx = tid + r * 128;
            const float4 f = qsrc[idx];
            const int row = idx >> 3;
            const int c4  = (idx & 7) * 4;
            float4 t;
            t.x = tfval(f.x * SCALE); t.y = tfval(f.y * SCALE);
            t.z = tfval(f.z * SCALE); t.w = tfval(f.w * SCALE);
            *(float4*)&Qs[row * 36 + c4] = t;
        }
        const float4* ksrc = (const float4*)(g_krot + bh * Ss * HD);
        const float4* vsrc = (const float4*)(g_v    + bh * Ss * HD);
        #pragma unroll
        for (int r = 0; r < 16; r++) {
            const int idx = tid + r * 128;
            const int key = idx >> 3;
            const int c4  = (idx & 7) * 4;
            const float4 fk = ksrc[idx];
            float4 tk;
            tk.x = tfval(fk.x); tk.y = tfval(fk.y); tk.z = tfval(fk.z); tk.w = tfval(fk.w);
            *(float4*)&Kf[key * 36 + c4] = tk;
            const float4 fv4 = vsrc[idx];
            float4 tv;
            tv.x = tfval(fv4.x); tv.y = tfval(fv4.y); tv.z = tfval(fv4.z); tv.w = tfval(fv4.w);
            *(float4*)&Vs[key * 40 + c4] = tv;
        }
    }
    __syncthreads();

    // ---- load Q a-frags (held for whole kernel) ----
    unsigned aq[4][4];
    #pragma unroll
    for (int ks = 0; ks < 4; ks++) {
        const int base = ks * 8 + tg;
        aq[ks][0] = __float_as_uint(Qs[qr * 36 + base]);
        aq[ks][1] = __float_as_uint(Qs[(qr + 8) * 36 + base]);
        aq[ks][2] = __float_as_uint(Qs[qr * 36 + base + 4]);
        aq[ks][3] = __float_as_uint(Qs[(qr + 8) * 36 + base + 4]);
    }

    float m0 = -1e30f, m1 = -1e30f, l0 = 0.0f, l1 = 0.0f;
    float o[4][4];
    #pragma unroll
    for (int nt = 0; nt < 4; nt++)
        #pragma unroll
        for (int i = 0; i < 4; i++) o[nt][i] = 0.0f;

    #pragma unroll
    for (int ch = 0; ch < 4; ch++) {
        // ---- QK^T for 64-key chunk ----
        float c[8][4];
        #pragma unroll
        for (int nt = 0; nt < 8; nt++)
            #pragma unroll
            for (int i = 0; i < 4; i++) c[nt][i] = 0.0f;

        #pragma unroll
        for (int nt = 0; nt < 8; nt++) {
            const int k0 = ch * 64 + nt * 8 + g;
            #pragma unroll
            for (int ks = 0; ks < 4; ks++) {
                const unsigned b0 = __float_as_uint(Kf[k0 * 36 + ks * 8 + tg]);
                const unsigned b1 = __float_as_uint(Kf[k0 * 36 + ks * 8 + tg + 4]);
                mma8(c[nt], aq[ks], b0, b1);
            }
        }

        // ---- chunk row max ----
        float cm0 = -1e30f, cm1 = -1e30f;
        #pragma unroll
        for (int nt = 0; nt < 8; nt++) {
            cm0 = fmaxf(cm0, fmaxf(c[nt][0], c[nt][1]));
            cm1 = fmaxf(cm1, fmaxf(c[nt][2], c[nt][3]));
        }
        cm0 = fmaxf(cm0, __shfl_xor_sync(0xffffffffu, cm0, 1));
        cm0 = fmaxf(cm0, __shfl_xor_sync(0xffffffffu, cm0, 2));
        cm1 = fmaxf(cm1, __shfl_xor_sync(0xffffffffu, cm1, 1));
        cm1 = fmaxf(cm1, __shfl_xor_sync(0xffffffffu, cm1, 2));

        float sc0 = 1.0f, sc1 = 1.0f;
        if (ch == 0) {
            m0 = cm0; m1 = cm1;
        } else {
            const float mn0 = fmaxf(m0, cm0);
            const float mn1 = fmaxf(m1, cm1);
            sc0 = __expf(m0 - mn0);
            sc1 = __expf(m1 - mn1);
            m0 = mn0; m1 = mn1;
        }

        // ---- exp + row sums; convert to tf32 probs ----
        float s0 = 0.0f, s1 = 0.0f;
        #pragma unroll
        for (int nt = 0; nt < 8; nt++) {
            const float p0 = __expf(c[nt][0] - m0);
            const float p1 = __expf(c[nt][1] - m0);
            const float p2 = __expf(c[nt][2] - m1);
            const float p3 = __expf(c[nt][3] - m1);
            s0 += p0 + p1;  s1 += p2 + p3;
            c[nt][0] = tfval(p0); c[nt][1] = tfval(p1);
            c[nt][2] = tfval(p2); c[nt][3] = tfval(p3);
        }
        s0 += __shfl_xor_sync(0xffffffffu, s0, 1);
        s0 += __shfl_xor_sync(0xffffffffu, s0, 2);
        s1 += __shfl_xor_sync(0xffffffffu, s1, 1);
        s1 += __shfl_xor_sync(0xffffffffu, s1, 2);
        if (ch == 0) {
            l0 = s0;  l1 = s1;
        } else {
            l0 = l0 * sc0 + s0;
            l1 = l1 * sc1 + s1;
            #pragma unroll
            for (int nt = 0; nt < 4; nt++) {
                o[nt][0] *= sc0;  o[nt][1] *= sc0;
                o[nt][2] *= sc1;  o[nt][3] *= sc1;
            }
        }

        // ---- write chunk probs to per-warp Ps rows ----
        #pragma unroll
        for (int nt = 0; nt < 8; nt++) {
            *(float2*)&Ps[qr * 68 + nt * 8 + 2 * tg]       = make_float2(c[nt][0], c[nt][1]);
            *(float2*)&Ps[(qr + 8) * 68 + nt * 8 + 2 * tg] = make_float2(c[nt][2], c[nt][3]);
        }
        __syncwarp();

        // ---- P @ V for this chunk ----
        #pragma unroll
        for (int s = 0; s < 8; s++) {
            unsigned a[4];
            a[0] = __float_as_uint(Ps[qr * 68 + s * 8 + tg]);
            a[1] = __float_as_uint(Ps[(qr + 8) * 68 + s * 8 + tg]);
            a[2] = __float_as_uint(Ps[qr * 68 + s * 8 + tg + 4]);
            a[3] = __float_as_uint(Ps[(qr + 8) * 68 + s * 8 + tg + 4]);
            const int kk = ch * 64 + s * 8;
            #pragma unroll
            for (int nt = 0; nt < 4; nt++) {
                const unsigned b0 = __float_as_uint(Vs[(kk + tg) * 40 + nt * 8 + g]);
                const unsigned b1 = __float_as_uint(Vs[(kk + tg + 4) * 40 + nt * 8 + g]);
                mma8(o[nt], a, b0, b1);
            }
        }
        __syncwarp();
    }

    // ---- epilogue: normalize + store ----
    const float r0 = 1.0f / l0;
    const float r1 = 1.0f / l1;
    #pragma unroll
    for (int nt = 0; nt < 4; nt++) {
        const int hd = nt * 8 + 2 * tg;
        float* p0 = g_att + ((size_t)(b * Nn + n0 + qr)) * Cch + h * HD + hd;
        float* p1 = g_att + ((size_t)(b * Nn + n0 + qr + 8)) * Cch + h * HD + hd;
        *(float2*)p0 = make_float2(o[nt][0] * r0, o[nt][1] * r0);
        *(float2*)p1 = make_float2(o[nt][2] * r1, o[nt][3] * r1);
    }
}

// ---------------------------------------------------------------------------
// Kernel 4: O projection + transpose, TF32 mma. CTA = 64 tokens x 256 cols.
// ---------------------------------------------------------------------------
__global__ void __launch_bounds__(256, 2) oproj_kernel(const float* __restrict__ ow,
                                                       const float* __restrict__ ob,
                                                       float* __restrict__ out)
{
    extern __shared__ float sm[];
    float* As = sm + PJ_A;      // [64][36]
    float* Ws = sm + PJ_W;      // [32][264]

    const int tid  = threadIdx.x;
    const int w    = tid >> 5;
    const int lane = tid & 31;
    const int g    = lane >> 2;
    const int tg   = lane & 3;
    const int b    = blockIdx.x >> 9;
    const int n0   = (blockIdx.x & 511) << 6;
    const int mg   = w >> 2;
    const int cg   = w & 3;
    const int m0   = mg * 32;

    float acc[2][8][4];
    #pragma unroll
    for (int mt = 0; mt < 2; mt++)
        #pragma unroll
        for (int nt = 0; nt < 8; nt++)
            #pragma unroll
            for (int i = 0; i < 4; i++) acc[mt][nt][i] = 0.0f;

    for (int k0 = 0; k0 < Cch; k0 += 32) {
        // stage A from g_att (row-major)
        #pragma unroll
        for (int r = 0; r < 8; r++) {
            const int e  = tid + r * 256;
            const int nn = e >> 5;
            const int kk = e & 31;
            As[nn * 36 + kk] = tfval(g_att[((size_t)(b * Nn + n0 + nn)) * Cch + k0 + kk]);
        }
        // stage W row-major [32 k][256 c]
        #pragma unroll
        for (int r = 0; r < 8; r++) {
            const int e  = tid + r * 256;
            const int kk = e >> 6;
            const int c4 = (e & 63) * 4;
            const float4 f = *(const float4*)(ow + (size_t)(k0 + kk) * Cch + c4);
            float4 t;
            t.x = tfval(f.x); t.y = tfval(f.y); t.z = tfval(f.z); t.w = tfval(f.w);
            *(float4*)&Ws[kk * 264 + c4] = t;
        }
        __syncthreads();

        unsigned a[2][4][4];
        #pragma unroll
        for (int mt = 0; mt < 2; mt++) {
            const int row = m0 + mt * 16 + g;
            #pragma unroll
            for (int ks = 0; ks < 4; ks++) {
                const int base = ks * 8 + tg;
                a[mt][ks][0] = __float_as_uint(As[row * 36 + base]);
                a[mt][ks][1] = __float_as_uint(As[(row + 8) * 36 + base]);
                a[mt][ks][2] = __float_as_uint(As[row * 36 + base + 4]);
                a[mt][ks][3] = __float_as_uint(As[(row + 8) * 36 + base + 4]);
            }
        }
        #pragma unroll
        for (int nt = 0; nt < 8; nt++) {
            const int c0 = cg * 64 + nt * 8 + g;
            #pragma unroll
            for (int ks = 0; ks < 4; ks++) {
                const unsigned b0 = __float_as_uint(Ws[(ks * 8 + tg) * 264 + c0]);
                const unsigned b1 = __float_as_uint(Ws[(ks * 8 + tg + 4) * 264 + c0]);
                mma8(acc[0][nt], a[0][ks], b0, b1);
                mma8(acc[1][nt], a[1][ks], b0, b1);
            }
        }
        __syncthreads();
    }

    #pragma unroll
    for (int mt = 0; mt < 2; mt++) {
        const int row = m0 + mt * 16 + g;
        #pragma unroll
        for (int nt = 0; nt < 8; nt++) {
            const int col = cg * 64 + nt * 8 + 2 * tg;
            *(float2*)&sm[row * 258 + col]       = make_float2(acc[mt][nt][0], acc[mt][nt][1]);
            *(float2*)&sm[(row + 8) * 258 + col] = make_float2(acc[mt][nt][2], acc[mt][nt][3]);
        }
    }
    __syncthreads();

    // transposed coalesced store: out[b][c][n0 + token]
    const int grp = tid >> 5;
    float* __restrict__ obp = out + (size_t)b * Cch * Nn + n0 + lane;
    #pragma unroll 4
    for (int it = 0; it < 32; it++) {
        const int c = it * 8 + grp;
        const float bias = ob[c];
        obp[(size_t)c * Nn]      = sm[lane * 258 + c] + bias;
        obp[(size_t)c * Nn + 32] = sm[(lane + 32) * 258 + c] + bias;
    }
}

// ---------------------------------------------------------------------------
extern "C" void kernel_launch(void* const* d_in, const int* in_sizes, int n_in,
                              void* d_out, int out_size)
{
    const float* fused_visual = (const float*)d_in[0];
    const float* text_emb     = (const float*)d_in[1];
    const float* q_w = (const float*)d_in[2];
    const float* q_b = (const float*)d_in[3];
    const float* k_w = (const float*)d_in[4];
    const float* k_b = (const float*)d_in[5];
    const float* v_w = (const float*)d_in[6];
    const float* v_b = (const float*)d_in[7];
    const float* o_w = (const float*)d_in[8];
    const float* o_b = (const float*)d_in[9];
    const float* m1_w = (const float*)d_in[10];
    const float* m1_b = (const float*)d_in[11];
    const float* m2_w = (const float*)d_in[12];
    const float* m2_b = (const float*)d_in[13];
    float* out = (float*)d_out;

    static int smem_ok = -1;
    if (smem_ok < 0) {
        cudaFuncSetAttribute(attn_kernel,  cudaFuncAttributeMaxDynamicSharedMemorySize, AT_BYTES);
        cudaFuncSetAttribute(qproj_kernel, cudaFuncAttributeMaxDynamicSharedMemorySize, QJ_BYTES);
        cudaFuncSetAttribute(oproj_kernel, cudaFuncAttributeMaxDynamicSharedMemorySize, OJ_BYTES);
        smem_ok = 1;
    }

    text_kernel<<<(Bv * Ss) / 8, 256>>>(text_emb, k_w, k_b, v_w, v_b, m1_w, m1_b, m2_w, m2_b);
    qproj_kernel<<<Bv * (Nn / 64), 256, QJ_BYTES>>>(fused_visual, q_w, q_b);
    attn_kernel<<<dim3(Nn / 64, NH, Bv), 128, AT_BYTES>>>();
    oproj_kernel<<<Bv * (Nn / 64), 256, OJ_BYTES>>>(o_w, o_b, out);
}

// round 10
// speedup vs baseline: 4.8445x; 1.2065x over previous
#include <cuda_runtime.h>
#include <math.h>

// ---------------- problem constants ----------------
#define Bv   2
#define Cch  256
#define Nn   32768           // D*H*W
#define Ss   256
#define TDd  512
#define NH   8
#define HD   32
#define SCALE 0.17677669529663687f   // 32^-0.5

// ---------------- scratch ----------------
__device__ float g_krot[Bv * NH * Ss * HD];          // [b,h,s,hd]
__device__ float g_v   [Bv * NH * Ss * HD];          // [b,h,s,hd]
__device__ float g_qrot[(size_t)Bv * NH * Nn * HD];  // [b,h,n,hd]  64MB
__device__ float g_att [(size_t)Bv * Nn * Cch];      // [b,n,c]     64MB

// ---------------- helpers ----------------
__device__ __forceinline__ unsigned f2tf(float x) {
    unsigned u;
    asm("cvt.rna.tf32.f32 %0, %1;" : "=r"(u) : "f"(x));
    return u;
}
__device__ __forceinline__ float tfval(float x) { return __uint_as_float(f2tf(x)); }

__device__ __forceinline__ void mma8(float c[4], const unsigned a[4],
                                     unsigned b0, unsigned b1) {
    asm volatile(
        "mma.sync.aligned.m16n8k8.row.col.f32.tf32.tf32.f32 "
        "{%0,%1,%2,%3},{%4,%5,%6,%7},{%8,%9},{%0,%1,%2,%3};"
        : "+f"(c[0]), "+f"(c[1]), "+f"(c[2]), "+f"(c[3])
        : "r"(a[0]), "r"(a[1]), "r"(a[2]), "r"(a[3]), "r"(b0), "r"(b1));
}

__device__ __forceinline__ void cpasync16(unsigned dst, const void* src) {
    asm volatile("cp.async.ca.shared.global [%0], [%1], 16;" :: "r"(dst), "l"(src));
}
#define CP_COMMIT()  asm volatile("cp.async.commit_group;")
#define CP_WAIT(n)   asm volatile("cp.async.wait_group %0;" :: "n"(n))

// ---------------------------------------------------------------------------
// Kernel 1: text side (K/V proj, MLP phase, rope on K). 64 CTAs, tiny. FFMA.
// ---------------------------------------------------------------------------
__global__ void text_kernel(const float* __restrict__ text,
                            const float* __restrict__ k_w, const float* __restrict__ k_b,
                            const float* __restrict__ v_w, const float* __restrict__ v_b,
                            const float* __restrict__ m1_w, const float* __restrict__ m1_b,
                            const float* __restrict__ m2_w, const float* __restrict__ m2_b)
{
    __shared__ float t_s[8][TDd];
    __shared__ float h_s[8][Cch];
    __shared__ float k_s[8][Cch];

    const int tid  = threadIdx.x;
    const int row0 = blockIdx.x * 8;

    #pragma unroll
    for (int r = 0; r < 8; r++) {
        t_s[r][tid]       = text[(size_t)(row0 + r) * TDd + tid];
        t_s[r][tid + 256] = text[(size_t)(row0 + r) * TDd + tid + 256];
    }
    __syncthreads();

    float ka[8], va[8], ha[8];
    #pragma unroll
    for (int r = 0; r < 8; r++) { ka[r] = k_b[tid]; va[r] = v_b[tid]; ha[r] = m1_b[tid]; }

    for (int i = 0; i < TDd; i++) {
        const float wk = k_w[i * Cch + tid];
        const float wv = v_w[i * Cch + tid];
        const float wm = m1_w[i * Cch + tid];
        #pragma unroll
        for (int r = 0; r < 8; r++) {
            const float t = t_s[r][i];
            ka[r] += t * wk;  va[r] += t * wv;  ha[r] += t * wm;
        }
    }

    #pragma unroll
    for (int r = 0; r < 8; r++) {
        const float x = ha[r];
        h_s[r][tid] = 0.5f * x * (1.0f + erff(x * 0.7071067811865475f));
        k_s[r][tid] = ka[r];
    }
    __syncthreads();

    float pa[8];
    #pragma unroll
    for (int r = 0; r < 8; r++) pa[r] = m2_b[tid];
    for (int i = 0; i < Cch; i++) {
        const float wm2 = m2_w[i * Cch + tid];
        #pragma unroll
        for (int r = 0; r < 8; r++) pa[r] += h_s[r][i] * wm2;
    }

    const int j    = tid & 31;
    const int head = tid >> 5;
    const int part = (j < 16) ? tid + 16 : tid - 16;
    const float sgn = (j < 16) ? -1.0f : 1.0f;

    #pragma unroll
    for (int r = 0; r < 8; r++) {
        const int row = row0 + r;
        const int b = row >> 8;
        const int s = row & 255;
        float sf, cf;
        sincosf(pa[r], &sf, &cf);
        const float krot = k_s[r][tid] * cf + sgn * k_s[r][part] * sf;
        const int o = ((b * NH + head) * Ss + s) * HD + j;
        g_krot[o] = krot;
        g_v[o]    = va[r];
    }
}

// ---------------------------------------------------------------------------
// Projection kernels: TF32 mma, cp.async double-buffered staging.
// CTA = 64 tokens x 256 cols, 256 threads; warp tile 32x64.
// qproj A layout: [k][token] stride 72 (direct cp.async of fv rows).
// oproj A layout: [token][k] stride 36 (direct cp.async of g_att rows).
// W layout: [k][col] stride 264. All fragment loads conflict-free.
// tf32 conversion happens at fragment-load time (cvt.rna).
// ---------------------------------------------------------------------------
#define QA0  0
#define QA1  2304            // 32*72
#define QW0  4608
#define QW1  13056           // +32*264
#define QTB  21504           // rope tables cos[1024]|sin[1024]
#define QJ_FLOATS 23552
#define QJ_BYTES (QJ_FLOATS * 4)

#define OA0  0
#define OA1  2304            // 64*36
#define OW0  4608
#define OW1  13056
#define OJ_FLOATS 21504
#define OJ_BYTES (OJ_FLOATS * 4)

__global__ void __launch_bounds__(256, 2) qproj_kernel(const float* __restrict__ fv,
                                                       const float* __restrict__ qw,
                                                       const float* __restrict__ qb)
{
    extern __shared__ float sm[];
    const unsigned smu = (unsigned)__cvta_generic_to_shared(sm);
    float* TB = sm + QTB;

    const int tid  = threadIdx.x;
    const int w    = tid >> 5;
    const int lane = tid & 31;
    const int g    = lane >> 2;
    const int tg   = lane & 3;
    const int b    = blockIdx.x >> 9;
    const int n0   = (blockIdx.x & 511) << 6;
    const int mg   = w >> 2;
    const int cg   = w & 3;
    const int m0   = mg * 32;

    // ---- build rope tables (4 sincos per thread) ----
    #pragma unroll
    for (int e = 0; e < 4; e++) {
        const int idx = tid + e * 256;
        const int pos = idx >> 5;
        const int jj  = idx & 31;
        float ex;
        if (jj < 10)      { const int z = jj;      ex = ((z < 5) ? z : z - 5) / 5.0f; }
        else if (jj < 20) { const int y = jj - 10; ex = ((y < 5) ? y : y - 5) / 5.0f; }
        else              { const int x = jj - 20; ex = ((x < 6) ? x : x - 6) / 6.0f; }
        const float invf = expf(-ex * 9.210340371976184f);
        float sf, cf;
        __sincosf((float)pos * invf, &sf, &cf);
        TB[idx]        = cf;
        TB[1024 + idx] = sf;
    }

    const float* __restrict__ fvb = fv + (size_t)b * Cch * Nn;

    // staging lambda-equivalents
    const int akk = (tid + 0) >> 4;          // reused pattern below

    float acc[2][8][4];
    #pragma unroll
    for (int mt = 0; mt < 2; mt++)
        #pragma unroll
        for (int nt = 0; nt < 8; nt++)
            #pragma unroll
            for (int i = 0; i < 4; i++) acc[mt][nt][i] = 0.0f;

    // prefetch iteration 0 into buffer 0
    {
        #pragma unroll
        for (int r = 0; r < 2; r++) {
            const int idx = tid + r * 256;
            const int kk = idx >> 4, cc = idx & 15;
            cpasync16(smu + (QA0 + kk * 72 + cc * 4) * 4,
                      fvb + (size_t)kk * Nn + n0 + cc * 4);
        }
        #pragma unroll
        for (int r = 0; r < 8; r++) {
            const int idx = tid + r * 256;
            const int kk = idx >> 6, cc = idx & 63;
            cpasync16(smu + (QW0 + kk * 264 + cc * 4) * 4,
                      qw + (size_t)kk * Cch + cc * 4);
        }
        CP_COMMIT();
    }

    for (int it = 0; it < 8; it++) {
        const int abuf = (it & 1) ? QA1 : QA0;
        const int wbuf = (it & 1) ? QW1 : QW0;
        if (it < 7) {
            const int k1 = (it + 1) * 32;
            const int a2 = (it & 1) ? QA0 : QA1;
            const int w2 = (it & 1) ? QW0 : QW1;
            #pragma unroll
            for (int r = 0; r < 2; r++) {
                const int idx = tid + r * 256;
                const int kk = idx >> 4, cc = idx & 15;
                cpasync16(smu + (a2 + kk * 72 + cc * 4) * 4,
                          fvb + (size_t)(k1 + kk) * Nn + n0 + cc * 4);
            }
            #pragma unroll
            for (int r = 0; r < 8; r++) {
                const int idx = tid + r * 256;
                const int kk = idx >> 6, cc = idx & 63;
                cpasync16(smu + (w2 + kk * 264 + cc * 4) * 4,
                          qw + (size_t)(k1 + kk) * Cch + cc * 4);
            }
            CP_COMMIT();
            CP_WAIT(1);
        } else {
            CP_WAIT(0);
        }
        __syncthreads();

        const float* As = sm + abuf;
        const float* Ws = sm + wbuf;

        unsigned a[2][4][4];
        #pragma unroll
        for (int mt = 0; mt < 2; mt++) {
            const int row = m0 + mt * 16 + g;
            #pragma unroll
            for (int ks = 0; ks < 4; ks++) {
                const int base = ks * 8 + tg;
                a[mt][ks][0] = f2tf(As[base * 72 + row]);
                a[mt][ks][1] = f2tf(As[base * 72 + row + 8]);
                a[mt][ks][2] = f2tf(As[(base + 4) * 72 + row]);
                a[mt][ks][3] = f2tf(As[(base + 4) * 72 + row + 8]);
            }
        }
        #pragma unroll
        for (int nt = 0; nt < 8; nt++) {
            const int c0 = cg * 64 + nt * 8 + g;
            #pragma unroll
            for (int ks = 0; ks < 4; ks++) {
                const unsigned b0 = f2tf(Ws[(ks * 8 + tg) * 264 + c0]);
                const unsigned b1 = f2tf(Ws[(ks * 8 + tg + 4) * 264 + c0]);
                mma8(acc[0][nt], a[0][ks], b0, b1);
                mma8(acc[1][nt], a[1][ks], b0, b1);
            }
        }
        __syncthreads();
    }

    // write accums into OUT[64][258] (overlays staging buffers)
    #pragma unroll
    for (int mt = 0; mt < 2; mt++) {
        const int row = m0 + mt * 16 + g;
        #pragma unroll
        for (int nt = 0; nt < 8; nt++) {
            const int col = cg * 64 + nt * 8 + 2 * tg;
            *(float2*)&sm[row * 258 + col]       = make_float2(acc[mt][nt][0], acc[mt][nt][1]);
            *(float2*)&sm[(row + 8) * 258 + col] = make_float2(acc[mt][nt][2], acc[mt][nt][3]);
        }
    }
    __syncthreads();

    // epilogue: bias + 3D rope via table; thread = channel c for 64 tokens
    const int c    = tid;
    const int j    = c & 31;
    const int head = c >> 5;
    const int sel  = (j < 10) ? 0 : (j < 20) ? 1 : 2;
    const int part  = (j < 16) ? c + 16 : c - 16;
    const float sgn = (j < 16) ? -1.0f : 1.0f;
    const float qbc = qb[c], qbp = qb[part];

    float* __restrict__ qo = g_qrot + (((size_t)(b * NH + head)) * Nn) * HD + j;
    for (int nn = 0; nn < 64; nn++) {
        const int n  = n0 + nn;
        const int dz = n >> 10;
        const int hy = (n >> 5) & 31;
        const int wx = n & 31;
        const int posv = (sel == 0) ? dz : (sel == 1) ? hy : wx;
        const float cf = TB[posv * 32 + j];
        const float sf = TB[1024 + posv * 32 + j];
        const float qv = sm[nn * 258 + c]    + qbc;
        const float pv = sm[nn * 258 + part] + qbp;
        qo[(size_t)n * HD] = qv * cf + sgn * pv * sf;
    }
}

// ---------------------------------------------------------------------------
// Kernel 3: flash-style attention, TF32 mma. CTA = 128 queries (8 warps),
// each warp owns 16 queries x full 256 keys, online softmax in registers.
// smem: union{Qs[128][36], Ps[128][68]} | Kf[256][36] | Vs[256][40] = 110KB
// -> 2 CTAs/SM (16 warps). Qs is dead after aq-load (guarded by one sync).
// ---------------------------------------------------------------------------
#define APQ  0                       // union: Qs (4608 fl) / Ps (8704 fl)
#define AK   8704
#define AV   (AK + 256*36)           // 17920
#define AT_FLOATS (AV + 256*40)      // 28160
#define AT_BYTES (AT_FLOATS * 4)     // 112640

__global__ void __launch_bounds__(256, 2) attn_kernel()
{
    extern __shared__ float sm[];
    float* Qs = sm + APQ;    // [128][36]  (staging only)
    float* Ps = sm + APQ;    // [128][68]  (after aq-load)
    float* Kf = sm + AK;     // [256][36]
    float* Vs = sm + AV;     // [256][40]

    const int tid  = threadIdx.x;
    const int w    = tid >> 5;       // 0..7
    const int lane = tid & 31;
    const int g    = lane >> 2;
    const int tg   = lane & 3;
    const int n0   = blockIdx.x * 128;
    const int h    = blockIdx.y;
    const int b    = blockIdx.z;
    const size_t bh = (size_t)(b * NH + h);
    const int qr   = w * 16 + g;

    // ---- stage Q (scaled + tf32), K, V ----
    {
        const float4* qsrc = (const float4*)(g_qrot + (bh * Nn + n0) * HD);
        #pragma unroll
        for (int r = 0; r < 4; r++) {
            const int idx = tid + r * 256;        // 0..1023
            const float4 f = qsrc[idx];
            const int row = idx >> 3;
            const int c4  = (idx & 7) * 4;
            float4 t;
            t.x = tfval(f.x * SCALE); t.y = tfval(f.y * SCALE);
            t.z = tfval(f.z * SCALE); t.w = tfval(f.w * SCALE);
            *(float4*)&Qs[row * 36 + c4] = t;
        }
        const float4* ksrc = (const float4*)(g_krot + bh * Ss * HD);
        const float4* vsrc = (const float4*)(g_v    + bh * Ss * HD);
        #pragma unroll
        for (int r = 0; r < 8; r++) {
            const int idx = tid + r * 256;        // 0..2047
            const int key = idx >> 3;
            const int c4  = (idx & 7) * 4;
            const float4 fk = ksrc[idx];
            float4 tk;
            tk.x = tfval(fk.x); tk.y = tfval(fk.y); tk.z = tfval(fk.z); tk.w = tfval(fk.w);
            *(float4*)&Kf[key * 36 + c4] = tk;
            const float4 fv4 = vsrc[idx];
            float4 tv;
            tv.x = tfval(fv4.x); tv.y = tfval(fv4.y); tv.z = tfval(fv4.z); tv.w = tfval(fv4.w);
            *(float4*)&Vs[key * 40 + c4] = tv;
        }
    }
    __syncthreads();

    // ---- load Q a-frags (held for whole kernel) ----
    unsigned aq[4][4];
    #pragma unroll
    for (int ks = 0; ks < 4; ks++) {
        const int base = ks * 8 + tg;
        aq[ks][0] = __float_as_uint(Qs[qr * 36 + base]);
        aq[ks][1] = __float_as_uint(Qs[(qr + 8) * 36 + base]);
        aq[ks][2] = __float_as_uint(Qs[qr * 36 + base + 4]);
        aq[ks][3] = __float_as_uint(Qs[(qr + 8) * 36 + base + 4]);
    }
    __syncthreads();   // Qs dead; Ps may now overlay it

    float m0 = -1e30f, m1 = -1e30f, l0 = 0.0f, l1 = 0.0f;
    float o[4][4];
    #pragma unroll
    for (int nt = 0; nt < 4; nt++)
        #pragma unroll
        for (int i = 0; i < 4; i++) o[nt][i] = 0.0f;

    #pragma unroll
    for (int ch = 0; ch < 4; ch++) {
        // ---- QK^T for 64-key chunk ----
        float c[8][4];
        #pragma unroll
        for (int nt = 0; nt < 8; nt++)
            #pragma unroll
            for (int i = 0; i < 4; i++) c[nt][i] = 0.0f;

        #pragma unroll
        for (int nt = 0; nt < 8; nt++) {
            const int k0 = ch * 64 + nt * 8 + g;
            #pragma unroll
            for (int ks = 0; ks < 4; ks++) {
                const unsigned b0 = __float_as_uint(Kf[k0 * 36 + ks * 8 + tg]);
                const unsigned b1 = __float_as_uint(Kf[k0 * 36 + ks * 8 + tg + 4]);
                mma8(c[nt], aq[ks], b0, b1);
            }
        }

        // ---- chunk row max ----
        float cm0 = -1e30f, cm1 = -1e30f;
        #pragma unroll
        for (int nt = 0; nt < 8; nt++) {
            cm0 = fmaxf(cm0, fmaxf(c[nt][0], c[nt][1]));
            cm1 = fmaxf(cm1, fmaxf(c[nt][2], c[nt][3]));
        }
        cm0 = fmaxf(cm0, __shfl_xor_sync(0xffffffffu, cm0, 1));
        cm0 = fmaxf(cm0, __shfl_xor_sync(0xffffffffu, cm0, 2));
        cm1 = fmaxf(cm1, __shfl_xor_sync(0xffffffffu, cm1, 1));
        cm1 = fmaxf(cm1, __shfl_xor_sync(0xffffffffu, cm1, 2));

        float sc0 = 1.0f, sc1 = 1.0f;
        if (ch == 0) {
            m0 = cm0; m1 = cm1;
        } else {
            const float mn0 = fmaxf(m0, cm0);
            const float mn1 = fmaxf(m1, cm1);
            sc0 = __expf(m0 - mn0);
            sc1 = __expf(m1 - mn1);
            m0 = mn0; m1 = mn1;
        }

        // ---- exp + row sums; convert to tf32 probs ----
        float s0 = 0.0f, s1 = 0.0f;
        #pragma unroll
        for (int nt = 0; nt < 8; nt++) {
            const float p0 = __expf(c[nt][0] - m0);
            const float p1 = __expf(c[nt][1] - m0);
            const float p2 = __expf(c[nt][2] - m1);
            const float p3 = __expf(c[nt][3] - m1);
            s0 += p0 + p1;  s1 += p2 + p3;
            c[nt][0] = tfval(p0); c[nt][1] = tfval(p1);
            c[nt][2] = tfval(p2); c[nt][3] = tfval(p3);
        }
        s0 += __shfl_xor_sync(0xffffffffu, s0, 1);
        s0 += __shfl_xor_sync(0xffffffffu, s0, 2);
        s1 += __shfl_xor_sync(0xffffffffu, s1, 1);
        s1 += __shfl_xor_sync(0xffffffffu, s1, 2);
        if (ch == 0) {
            l0 = s0;  l1 = s1;
        } else {
            l0 = l0 * sc0 + s0;
            l1 = l1 * sc1 + s1;
            #pragma unroll
            for (int nt = 0; nt < 4; nt++) {
                o[nt][0] *= sc0;  o[nt][1] *= sc0;
                o[nt][2] *= sc1;  o[nt][3] *= sc1;
            }
        }

        // ---- write chunk probs to per-warp Ps rows ----
        #pragma unroll
        for (int nt = 0; nt < 8; nt++) {
            *(float2*)&Ps[qr * 68 + nt * 8 + 2 * tg]       = make_float2(c[nt][0], c[nt][1]);
            *(float2*)&Ps[(qr + 8) * 68 + nt * 8 + 2 * tg] = make_float2(c[nt][2], c[nt][3]);
        }
        __syncwarp();

        // ---- P @ V for this chunk ----
        #pragma unroll
        for (int s = 0; s < 8; s++) {
            unsigned a[4];
            a[0] = __float_as_uint(Ps[qr * 68 + s * 8 + tg]);
            a[1] = __float_as_uint(Ps[(qr + 8) * 68 + s * 8 + tg]);
            a[2] = __float_as_uint(Ps[qr * 68 + s * 8 + tg + 4]);
            a[3] = __float_as_uint(Ps[(qr + 8) * 68 + s * 8 + tg + 4]);
            const int kk = ch * 64 + s * 8;
            #pragma unroll
            for (int nt = 0; nt < 4; nt++) {
                const unsigned b0 = __float_as_uint(Vs[(kk + tg) * 40 + nt * 8 + g]);
                const unsigned b1 = __float_as_uint(Vs[(kk + tg + 4) * 40 + nt * 8 + g]);
                mma8(o[nt], a, b0, b1);
            }
        }
        __syncwarp();
    }

    // ---- epilogue: normalize + store ----
    const float r0 = 1.0f / l0;
    const float r1 = 1.0f / l1;
    #pragma unroll
    for (int nt = 0; nt < 4; nt++) {
        const int hd = nt * 8 + 2 * tg;
        float* p0 = g_att + ((size_t)(b * Nn + n0 + qr)) * Cch + h * HD + hd;
        float* p1 = g_att + ((size_t)(b * Nn + n0 + qr + 8)) * Cch + h * HD + hd;
        *(float2*)p0 = make_float2(o[nt][0] * r0, o[nt][1] * r0);
        *(float2*)p1 = make_float2(o[nt][2] * r1, o[nt][3] * r1);
    }
}

// ---------------------------------------------------------------------------
// Kernel 4: O projection + transpose, TF32 mma, cp.async double-buffered.
// ---------------------------------------------------------------------------
__global__ void __launch_bounds__(256, 2) oproj_kernel(const float* __restrict__ ow,
                                                       const float* __restrict__ ob,
                                                       float* __restrict__ out)
{
    extern __shared__ float sm[];
    const unsigned smu = (unsigned)__cvta_generic_to_shared(sm);

    const int tid  = threadIdx.x;
    const int w    = tid >> 5;
    const int lane = tid & 31;
    const int g    = lane >> 2;
    const int tg   = lane & 3;
    const int b    = blockIdx.x >> 9;
    const int n0   = (blockIdx.x & 511) << 6;
    const int mg   = w >> 2;
    const int cg   = w & 3;
    const int m0   = mg * 32;

    const float* __restrict__ att = g_att + ((size_t)(b * Nn + n0)) * Cch;

    float acc[2][8][4];
    #pragma unroll
    for (int mt = 0; mt < 2; mt++)
        #pragma unroll
        for (int nt = 0; nt < 8; nt++)
            #pragma unroll
            for (int i = 0; i < 4; i++) acc[mt][nt][i] = 0.0f;

    // prefetch iter 0 into buffer 0
    {
        #pragma unroll
        for (int r = 0; r < 2; r++) {
            const int idx = tid + r * 256;       // 0..511
            const int nn = idx >> 3, cc = idx & 7;
            cpasync16(smu + (OA0 + nn * 36 + cc * 4) * 4,
                      att + (size_t)nn * Cch + cc * 4);
        }
        #pragma unroll
        for (int r = 0; r < 8; r++) {
            const int idx = tid + r * 256;
            const int kk = idx >> 6, cc = idx & 63;
            cpasync16(smu + (OW0 + kk * 264 + cc * 4) * 4,
                      ow + (size_t)kk * Cch + cc * 4);
        }
        CP_COMMIT();
    }

    for (int it = 0; it < 8; it++) {
        const int abuf = (it & 1) ? OA1 : OA0;
        const int wbuf = (it & 1) ? OW1 : OW0;
        if (it < 7) {
            const int k1 = (it + 1) * 32;
            const int a2 = (it & 1) ? OA0 : OA1;
            const int w2 = (it & 1) ? OW0 : OW1;
            #pragma unroll
            for (int r = 0; r < 2; r++) {
                const int idx = tid + r * 256;
                const int nn = idx >> 3, cc = idx & 7;
                cpasync16(smu + (a2 + nn * 36 + cc * 4) * 4,
                          att + (size_t)nn * Cch + k1 + cc * 4);
            }
            #pragma unroll
            for (int r = 0; r < 8; r++) {
                const int idx = tid + r * 256;
                const int kk = idx >> 6, cc = idx & 63;
                cpasync16(smu + (w2 + kk * 264 + cc * 4) * 4,
                          ow + (size_t)(k1 + kk) * Cch + cc * 4);
            }
            CP_COMMIT();
            CP_WAIT(1);
        } else {
            CP_WAIT(0);
        }
        __syncthreads();

        const float* As = sm + abuf;
        const float* Ws = sm + wbuf;

        unsigned a[2][4][4];
        #pragma unroll
        for (int mt = 0; mt < 2; mt++) {
            const int row = m0 + mt * 16 + g;
            #pragma unroll
            for (int ks = 0; ks < 4; ks++) {
                const int base = ks * 8 + tg;
                a[mt][ks][0] = f2tf(As[row * 36 + base]);
                a[mt][ks][1] = f2tf(As[(row + 8) * 36 + base]);
                a[mt][ks][2] = f2tf(As[row * 36 + base + 4]);
                a[mt][ks][3] = f2tf(As[(row + 8) * 36 + base + 4]);
            }
        }
        #pragma unroll
        for (int nt = 0; nt < 8; nt++) {
            const int c0 = cg * 64 + nt * 8 + g;
            #pragma unroll
            for (int ks = 0; ks < 4; ks++) {
                const unsigned b0 = f2tf(Ws[(ks * 8 + tg) * 264 + c0]);
                const unsigned b1 = f2tf(Ws[(ks * 8 + tg + 4) * 264 + c0]);
                mma8(acc[0][nt], a[0][ks], b0, b1);
                mma8(acc[1][nt], a[1][ks], b0, b1);
            }
        }
        __syncthreads();
    }

    #pragma unroll
    for (int mt = 0; mt < 2; mt++) {
        const int row = m0 + mt * 16 + g;
        #pragma unroll
        for (int nt = 0; nt < 8; nt++) {
            const int col = cg * 64 + nt * 8 + 2 * tg;
            *(float2*)&sm[row * 258 + col]       = make_float2(acc[mt][nt][0], acc[mt][nt][1]);
            *(float2*)&sm[(row + 8) * 258 + col] = make_float2(acc[mt][nt][2], acc[mt][nt][3]);
        }
    }
    __syncthreads();

    // transposed coalesced store: out[b][c][n0 + token]
    const int grp = tid >> 5;
    float* __restrict__ obp = out + (size_t)b * Cch * Nn + n0 + lane;
    #pragma unroll 4
    for (int it = 0; it < 32; it++) {
        const int c = it * 8 + grp;
        const float bias = ob[c];
        obp[(size_t)c * Nn]      = sm[lane * 258 + c] + bias;
        obp[(size_t)c * Nn + 32] = sm[(lane + 32) * 258 + c] + bias;
    }
}

// ---------------------------------------------------------------------------
extern "C" void kernel_launch(void* const* d_in, const int* in_sizes, int n_in,
                              void* d_out, int out_size)
{
    const float* fused_visual = (const float*)d_in[0];
    const float* text_emb     = (const float*)d_in[1];
    const float* q_w = (const float*)d_in[2];
    const float* q_b = (const float*)d_in[3];
    const float* k_w = (const float*)d_in[4];
    const float* k_b = (const float*)d_in[5];
    const float* v_w = (const float*)d_in[6];
    const float* v_b = (const float*)d_in[7];
    const float* o_w = (const float*)d_in[8];
    const float* o_b = (const float*)d_in[9];
    const float* m1_w = (const float*)d_in[10];
    const float* m1_b = (const float*)d_in[11];
    const float* m2_w = (const float*)d_in[12];
    const float* m2_b = (const float*)d_in[13];
    float* out = (float*)d_out;

    static int smem_ok = -1;
    if (smem_ok < 0) {
        cudaFuncSetAttribute(attn_kernel,  cudaFuncAttributeMaxDynamicSharedMemorySize, AT_BYTES);
        cudaFuncSetAttribute(qproj_kernel, cudaFuncAttributeMaxDynamicSharedMemorySize, QJ_BYTES);
        cudaFuncSetAttribute(oproj_kernel, cudaFuncAttributeMaxDynamicSharedMemorySize, OJ_BYTES);
        smem_ok = 1;
    }

    text_kernel<<<(Bv * Ss) / 8, 256>>>(text_emb, k_w, k_b, v_w, v_b, m1_w, m1_b, m2_w, m2_b);
    qproj_kernel<<<Bv * (Nn / 64), 256, QJ_BYTES>>>(fused_visual, q_w, q_b);
    attn_kernel<<<dim3(Nn / 128, NH, Bv), 256, AT_BYTES>>>();
    oproj_kernel<<<Bv * (Nn / 64), 256, OJ_BYTES>>>(o_w, o_b, out);
}